// round 1
// baseline (speedup 1.0000x reference)
#include <cuda_runtime.h>
#include <cuda_bf16.h>
#include <mma.h>
#include <math.h>

using namespace nvcuda;

// Problem constants
#define BB 2
#define TT 2048
#define DD 1024
#define HH 16
#define HD 64
#define MROWS (BB*TT)        // 4096

// Scratch (device globals; allocation is forbidden)
__device__ float g_Q[BB*HH*TT*HD];   // [B,H,T,hd], pre-scaled by 1/8
__device__ float g_K[BB*HH*TT*HD];
__device__ float g_V[BB*HH*TT*HD];
__device__ float g_O[MROWS*DD];      // [B*T, D]

typedef wmma::fragment<wmma::matrix_a, 16, 16, 8, wmma::precision::tf32, wmma::row_major> FragA;
typedef wmma::fragment<wmma::matrix_b, 16, 16, 8, wmma::precision::tf32, wmma::row_major> FragB;
typedef wmma::fragment<wmma::matrix_b, 16, 16, 8, wmma::precision::tf32, wmma::col_major> FragBT;
typedef wmma::fragment<wmma::accumulator, 16, 16, 8, float> FragC;

template <class F>
__device__ __forceinline__ void to_tf32(F& f) {
#pragma unroll
    for (int i = 0; i < f.num_elements; i++) f.x[i] = wmma::__float_to_tf32(f.x[i]);
}

// ---------------------------------------------------------------------------
// 128x64 output tile GEMM core: C = X[4096,1024] @ W[1024,1024] tile
// block = 256 threads (8 warps, 4x2), result left in Csm [128][64]
// ---------------------------------------------------------------------------
__device__ void gemm128x64(const float* __restrict__ X, const float* __restrict__ W,
                           float* Asm, float* Wsm, float* Csm, int m0, int n0)
{
    const int tid = threadIdx.x;
    const int w   = tid >> 5;
    const int wm  = w >> 1;     // 0..3
    const int wn  = w & 1;      // 0..1

    FragC acc[2][2];
#pragma unroll
    for (int i = 0; i < 2; i++)
#pragma unroll
        for (int j = 0; j < 2; j++) wmma::fill_fragment(acc[i][j], 0.0f);

    for (int k0 = 0; k0 < DD; k0 += 16) {
        __syncthreads();
        // A tile: 128 rows x 16 cols -> 512 float4
#pragma unroll
        for (int f = tid; f < 512; f += 256) {
            int r = f >> 2, c4 = f & 3;
            ((float4*)Asm)[f] =
                *(const float4*)(X + (size_t)(m0 + r) * DD + k0 + (c4 << 2));
        }
        // W tile: 16 rows x 64 cols -> 256 float4
        {
            int r = tid >> 4, c4 = tid & 15;
            ((float4*)Wsm)[tid] =
                *(const float4*)(W + (size_t)(k0 + r) * DD + n0 + (c4 << 2));
        }
        __syncthreads();

#pragma unroll
        for (int ks = 0; ks < 2; ks++) {
            FragA a[2];
            FragB bf[2];
#pragma unroll
            for (int i = 0; i < 2; i++) {
                wmma::load_matrix_sync(a[i], Asm + (size_t)(wm * 32 + i * 16) * 16 + ks * 8, 16);
                to_tf32(a[i]);
            }
#pragma unroll
            for (int j = 0; j < 2; j++) {
                wmma::load_matrix_sync(bf[j], Wsm + (size_t)(ks * 8) * 64 + wn * 32 + j * 16, 64);
                to_tf32(bf[j]);
            }
#pragma unroll
            for (int i = 0; i < 2; i++)
#pragma unroll
                for (int j = 0; j < 2; j++)
                    wmma::mma_sync(acc[i][j], a[i], bf[j], acc[i][j]);
        }
    }
    __syncthreads();
#pragma unroll
    for (int i = 0; i < 2; i++)
#pragma unroll
        for (int j = 0; j < 2; j++)
            wmma::store_matrix_sync(Csm + (size_t)(wm * 32 + i * 16) * 64 + wn * 32 + j * 16,
                                    acc[i][j], 64, wmma::mem_row_major);
    __syncthreads();
}

// ---------------------------------------------------------------------------
// QKV projection: grid (32, 16, 3), block 256
// z=0: Q = (query@Wq+bq)*0.125 -> g_Q ; z=1: K -> g_K ; z=2: V -> g_V
// output layout [B,H,T,hd]
// ---------------------------------------------------------------------------
__global__ __launch_bounds__(256)
void qkv_kernel(const float* __restrict__ q, const float* __restrict__ k,
                const float* __restrict__ v,
                const float* __restrict__ Wq, const float* __restrict__ Wk,
                const float* __restrict__ Wv,
                const float* __restrict__ bq, const float* __restrict__ bk,
                const float* __restrict__ bv)
{
    __shared__ float Asm[128 * 16];
    __shared__ float Wsm[16 * 64];
    __shared__ float Csm[128 * 64];

    const int z = blockIdx.z;
    const float* X    = (z == 0) ? q  : (z == 1) ? k  : v;
    const float* W    = (z == 0) ? Wq : (z == 1) ? Wk : Wv;
    const float* bias = (z == 0) ? bq : (z == 1) ? bk : bv;
    float* Out        = (z == 0) ? g_Q : (z == 1) ? g_K : g_V;
    const float scale = (z == 0) ? 0.125f : 1.0f;   // hd^-0.5 folded into Q

    const int m0 = blockIdx.x * 128;
    const int n0 = blockIdx.y * 64;

    gemm128x64(X, W, Asm, Wsm, Csm, m0, n0);

    const int tid = threadIdx.x;
#pragma unroll
    for (int f = tid; f < 2048; f += 256) {
        int flat = f << 2;
        int r = flat >> 6, c = flat & 63;
        float4 val = ((float4*)Csm)[f];
        int gm = m0 + r, gn = n0 + c;
        float4 bb = *(const float4*)(bias + gn);
        val.x = (val.x + bb.x) * scale;
        val.y = (val.y + bb.y) * scale;
        val.z = (val.z + bb.z) * scale;
        val.w = (val.w + bb.w) * scale;
        int bi = gm >> 11, t = gm & (TT - 1);
        int h  = gn >> 6,  d = gn & 63;
        *(float4*)(Out + ((((size_t)(bi * HH + h)) * TT + t) << 6) + d) = val;
    }
}

// ---------------------------------------------------------------------------
// Output projection: out = g_O @ Wo + bo, grid (32,16), block 256
// ---------------------------------------------------------------------------
__global__ __launch_bounds__(256)
void out_kernel(const float* __restrict__ Wo, const float* __restrict__ bo,
                float* __restrict__ out)
{
    __shared__ float Asm[128 * 16];
    __shared__ float Wsm[16 * 64];
    __shared__ float Csm[128 * 64];

    const int m0 = blockIdx.x * 128;
    const int n0 = blockIdx.y * 64;

    gemm128x64(g_O, Wo, Asm, Wsm, Csm, m0, n0);

    const int tid = threadIdx.x;
#pragma unroll
    for (int f = tid; f < 2048; f += 256) {
        int flat = f << 2;
        int r = flat >> 6, c = flat & 63;
        float4 val = ((float4*)Csm)[f];
        int gm = m0 + r, gn = n0 + c;
        float4 bb = *(const float4*)(bo + gn);
        val.x += bb.x; val.y += bb.y; val.z += bb.z; val.w += bb.w;
        *(float4*)(out + (size_t)gm * DD + gn) = val;
    }
}

// ---------------------------------------------------------------------------
// Flash attention with ALiBi. grid (T/64=32, H=16, B=2), block 128 (4 warps).
// Each warp owns 16 q-rows. K/V tiles of 64 rows staged in smem.
// O accumulator kept in smem (fp32) so per-row rescaling is layout-safe.
// ---------------------------------------------------------------------------
__global__ __launch_bounds__(128)
void attn_kernel()
{
    extern __shared__ float sm[];
    float* Ksm  = sm;              // 64*64
    float* Vsm  = sm + 4096;       // 64*64
    float* SP   = sm + 8192;       // 64*64 (Q staging, then S/P)
    float* Osm  = sm + 12288;      // 64*64
    float* mrow = sm + 16384;      // 64
    float* lrow = sm + 16448;      // 64

    const int qt = blockIdx.x;
    const int h  = blockIdx.y;
    const int b  = blockIdx.z;

    const int tid  = threadIdx.x;
    const int lane = tid & 31;
    const int w    = tid >> 5;

    const float* Qbase = g_Q + (((size_t)(b * HH + h)) * TT + qt * 64) * HD;
    const float* Kbase = g_K + (((size_t)(b * HH + h)) * TT) * HD;
    const float* Vbase = g_V + (((size_t)(b * HH + h)) * TT) * HD;

    // stage Q into SP, zero O, init m/l
#pragma unroll
    for (int i = tid; i < 1024; i += 128)
        ((float4*)SP)[i] = ((const float4*)Qbase)[i];
    float4 z4 = make_float4(0.f, 0.f, 0.f, 0.f);
#pragma unroll
    for (int i = tid; i < 1024; i += 128)
        ((float4*)Osm)[i] = z4;
    if (tid < 64) { mrow[tid] = -INFINITY; lrow[tid] = 0.0f; }
    __syncthreads();

    // Q fragments for this warp's 16 rows (Q already scaled by 0.125)
    FragA qf[8];
#pragma unroll
    for (int kk = 0; kk < 8; kk++) {
        wmma::load_matrix_sync(qf[kk], SP + (size_t)(w * 16) * 64 + kk * 8, 64);
        to_tf32(qf[kk]);
    }

    const float slope = exp2f(-0.5f * (float)(h + 1));

    const int r16  = lane >> 1;
    const int half = lane & 1;
    const int lr   = w * 16 + r16;
    const int qglob = qt * 64 + lr;
    const int rotbase = r16 + (half << 4);

    for (int kt = 0; kt < TT / 64; kt++) {
        __syncthreads();   // protect SP (iter 0) and K/V reuse
        // load K,V tiles (each 4096 contiguous floats)
        const float4* Kg = (const float4*)(Kbase + (size_t)kt * 4096);
        const float4* Vg = (const float4*)(Vbase + (size_t)kt * 4096);
#pragma unroll
        for (int i = tid; i < 1024; i += 128) {
            ((float4*)Ksm)[i] = Kg[i];
            ((float4*)Vsm)[i] = Vg[i];
        }
        __syncthreads();

        // ---- S = Q @ K^T (16 x 64 per warp) ----
#pragma unroll
        for (int n = 0; n < 4; n++) {
            FragC acc;
            wmma::fill_fragment(acc, 0.0f);
#pragma unroll
            for (int kk = 0; kk < 8; kk++) {
                FragBT bf;
                wmma::load_matrix_sync(bf, Ksm + (size_t)(n * 16) * 64 + kk * 8, 64);
                to_tf32(bf);
                wmma::mma_sync(acc, qf[kk], bf, acc);
            }
            wmma::store_matrix_sync(SP + (size_t)(w * 16) * 64 + n * 16, acc, 64,
                                    wmma::mem_row_major);
        }
        __syncwarp();

        // ---- online softmax with ALiBi on this warp's 16 rows ----
        float* Srow = SP + (size_t)lr * 64 + half * 32;
        float mx = -INFINITY;
#pragma unroll
        for (int it = 0; it < 32; it++) {
            int cc = (rotbase + it) & 31;
            int j = kt * 64 + half * 32 + cc;
            int di = qglob - j;
            float val = Srow[cc] + slope * (-(float)abs(di));
            Srow[cc] = val;
            mx = fmaxf(mx, val);
        }
        mx = fmaxf(mx, __shfl_xor_sync(0xffffffffu, mx, 1));
        float mprev = mrow[lr];
        float mnew  = fmaxf(mprev, mx);
        float corr  = __expf(mprev - mnew);

        float s = 0.0f;
#pragma unroll
        for (int it = 0; it < 32; it++) {
            int cc = (rotbase + it) & 31;
            float p = __expf(Srow[cc] - mnew);
            Srow[cc] = p;
            s += p;
        }
        s += __shfl_xor_sync(0xffffffffu, s, 1);
        if (half == 0) {
            mrow[lr] = mnew;
            lrow[lr] = lrow[lr] * corr + s;
        }
        // rescale O rows
        float* Orow = Osm + (size_t)lr * 64 + half * 32;
#pragma unroll
        for (int it = 0; it < 32; it++) {
            int cc = (rotbase + it) & 31;
            Orow[cc] *= corr;
        }
        __syncwarp();

        // ---- O += P @ V ----
        FragA pf[8];
#pragma unroll
        for (int kk = 0; kk < 8; kk++) {
            wmma::load_matrix_sync(pf[kk], SP + (size_t)(w * 16) * 64 + kk * 8, 64);
            to_tf32(pf[kk]);
        }
#pragma unroll
        for (int n = 0; n < 4; n++) {
            FragC acc;
            wmma::load_matrix_sync(acc, Osm + (size_t)(w * 16) * 64 + n * 16, 64,
                                   wmma::mem_row_major);
#pragma unroll
            for (int kk = 0; kk < 8; kk++) {
                FragB vf;
                wmma::load_matrix_sync(vf, Vsm + (size_t)(kk * 8) * 64 + n * 16, 64);
                to_tf32(vf);
                wmma::mma_sync(acc, pf[kk], vf, acc);
            }
            wmma::store_matrix_sync(Osm + (size_t)(w * 16) * 64 + n * 16, acc, 64,
                                    wmma::mem_row_major);
        }
        __syncwarp();
    }

    __syncthreads();
    // epilogue: O /= l, write to g_O [B*T, D] at head column h*64
    float* outBase = g_O + ((size_t)(b * TT + qt * 64)) * DD + h * HD;
#pragma unroll
    for (int f = tid; f < 1024; f += 128) {
        int flat = f << 2;
        int r = flat >> 6, c = flat & 63;
        float inv = 1.0f / lrow[r];
        float4 o = ((float4*)Osm)[f];
        o.x *= inv; o.y *= inv; o.z *= inv; o.w *= inv;
        *(float4*)(outBase + (size_t)r * DD + c) = o;
    }
}

// ---------------------------------------------------------------------------
extern "C" void kernel_launch(void* const* d_in, const int* in_sizes, int n_in,
                              void* d_out, int out_size)
{
    const float* query = (const float*)d_in[0];
    const float* key_  = (const float*)d_in[1];
    const float* value = (const float*)d_in[2];
    const float* Wq    = (const float*)d_in[3];
    const float* bq    = (const float*)d_in[4];
    const float* Wk    = (const float*)d_in[5];
    const float* bk    = (const float*)d_in[6];
    const float* Wv    = (const float*)d_in[7];
    const float* bv    = (const float*)d_in[8];
    const float* Wo    = (const float*)d_in[9];
    const float* bo    = (const float*)d_in[10];
    float* out = (float*)d_out;

    const int ATTN_SMEM = (4 * 4096 + 128) * (int)sizeof(float);  // 66048 B
    cudaFuncSetAttribute(attn_kernel, cudaFuncAttributeMaxDynamicSharedMemorySize,
                         ATTN_SMEM);

    dim3 gqkv(MROWS / 128, DD / 64, 3);
    qkv_kernel<<<gqkv, 256>>>(query, key_, value, Wq, Wk, Wv, bq, bk, bv);

    dim3 gattn(TT / 64, HH, BB);
    attn_kernel<<<gattn, 128, ATTN_SMEM>>>();

    dim3 gout(MROWS / 128, DD / 64);
    out_kernel<<<gout, 256>>>(Wo, bo, out);
}

// round 2
// speedup vs baseline: 4.1008x; 4.1008x over previous
#include <cuda_runtime.h>
#include <cuda_bf16.h>
#include <math.h>
#include <stdint.h>

// Problem constants
#define BB 2
#define TT 2048
#define DD 1024
#define HH 16
#define HD 64
#define MROWS (BB*TT)        // 4096

// Scratch (device globals; allocation is forbidden)
__device__ float g_Q[BB*HH*TT*HD];   // [B,H,T,hd], pre-scaled by 1/8
__device__ float g_K[BB*HH*TT*HD];
__device__ float g_V[BB*HH*TT*HD];
__device__ float g_O[MROWS*DD];      // [B*T, D]

// ---------------------------------------------------------------------------
// tf32 helpers + raw mma
// ---------------------------------------------------------------------------
__device__ __forceinline__ uint32_t f2tf(float x) {
    uint32_t r;
    asm("cvt.rna.tf32.f32 %0, %1;" : "=r"(r) : "f"(x));
    return r;
}
__device__ __forceinline__ float tff(float x) { return __uint_as_float(f2tf(x)); }
__device__ __forceinline__ uint32_t fbits(float x) { return __float_as_uint(x); }

// D = A(16x8,row) * B(8x8,col) + D, tf32 in, f32 out
__device__ __forceinline__ void mma_tf32(float c[4], const uint32_t a[4],
                                         uint32_t b0, uint32_t b1) {
    asm volatile(
        "mma.sync.aligned.m16n8k8.row.col.f32.tf32.tf32.f32 "
        "{%0,%1,%2,%3},{%4,%5,%6,%7},{%8,%9},{%0,%1,%2,%3};\n"
        : "+f"(c[0]), "+f"(c[1]), "+f"(c[2]), "+f"(c[3])
        : "r"(a[0]), "r"(a[1]), "r"(a[2]), "r"(a[3]), "r"(b0), "r"(b1));
}

// ---------------------------------------------------------------------------
// GEMM core: 128x128 block tile, BK=32, double-buffered.
// 256 threads = 8 warps arranged 4(m) x 2(n); warp tile 32x64.
// Asm: [2][128][36] (36 = 4 mod 32 -> conflict-free A-frag loads)
// Wsm: [2][32][136] (136 = 8 mod 32 -> conflict-free B-frag loads)
// ---------------------------------------------------------------------------
#define LDA 36
#define LDW 136
#define ASZ (128*LDA)
#define WSZ (32*LDW)
#define GEMM_SMEM_BYTES ((2*(ASZ+WSZ))*4)   // 71680

__device__ __forceinline__ void gemm128x128(
    const float* __restrict__ X, const float* __restrict__ W,
    int m0, int n0, float* Asm, float* Wsm, float acc[2][8][4])
{
    const int tid  = threadIdx.x;
    const int lane = tid & 31;
    const int w    = tid >> 5;
    const int wm   = w >> 1;      // 0..3
    const int wn   = w & 1;       // 0..1
    const int gr   = lane >> 2;   // 0..7
    const int gq   = lane & 3;    // 0..3

#pragma unroll
    for (int mt = 0; mt < 2; mt++)
#pragma unroll
        for (int nt = 0; nt < 8; nt++)
#pragma unroll
            for (int i = 0; i < 4; i++) acc[mt][nt][i] = 0.0f;

    float4 ar[4], wr[4];

    // loaders: A tile 128x32 (1024 float4), W tile 32x128 (1024 float4)
    auto LDGA = [&](int k0) {
#pragma unroll
        for (int j = 0; j < 4; j++) {
            int f  = tid + j * 256;
            int r  = f >> 3, c  = (f & 7) << 2;
            ar[j] = *(const float4*)(X + (size_t)(m0 + r) * DD + k0 + c);
            int rw = f >> 5, cw = (f & 31) << 2;
            wr[j] = *(const float4*)(W + (size_t)(k0 + rw) * DD + n0 + cw);
        }
    };
    auto STS = [&](int buf) {
        float* Ab = Asm + buf * ASZ;
        float* Wb = Wsm + buf * WSZ;
#pragma unroll
        for (int j = 0; j < 4; j++) {
            int f = tid + j * 256;
            int r = f >> 3, c = (f & 7) << 2;
            float4 v = ar[j];
            float4 vt = make_float4(tff(v.x), tff(v.y), tff(v.z), tff(v.w));
            *(float4*)(Ab + r * LDA + c) = vt;
            int rw = f >> 5, cw = (f & 31) << 2;
            float4 u = wr[j];
            float4 ut = make_float4(tff(u.x), tff(u.y), tff(u.z), tff(u.w));
            *(float4*)(Wb + rw * LDW + cw) = ut;
        }
    };

    LDGA(0);
    STS(0);
    __syncthreads();

#pragma unroll 1
    for (int s = 0; s < 32; s++) {
        if (s < 31) LDGA((s + 1) * 32);

        const float* Ab = Asm + (s & 1) * ASZ;
        const float* Wb = Wsm + (s & 1) * WSZ;

#pragma unroll
        for (int ks = 0; ks < 4; ks++) {
            uint32_t a[2][4];
#pragma unroll
            for (int mt = 0; mt < 2; mt++) {
                int r = wm * 32 + mt * 16;
                a[mt][0] = fbits(Ab[(r + gr)     * LDA + ks * 8 + gq]);
                a[mt][1] = fbits(Ab[(r + 8 + gr) * LDA + ks * 8 + gq]);
                a[mt][2] = fbits(Ab[(r + gr)     * LDA + ks * 8 + gq + 4]);
                a[mt][3] = fbits(Ab[(r + 8 + gr) * LDA + ks * 8 + gq + 4]);
            }
#pragma unroll
            for (int nt = 0; nt < 8; nt++) {
                int col = wn * 64 + nt * 8;
                uint32_t b0 = fbits(Wb[(ks * 8 + gq)     * LDW + col + gr]);
                uint32_t b1 = fbits(Wb[(ks * 8 + gq + 4) * LDW + col + gr]);
                mma_tf32(acc[0][nt], a[0], b0, b1);
                mma_tf32(acc[1][nt], a[1], b0, b1);
            }
        }
        if (s < 31) STS((s + 1) & 1);
        __syncthreads();
    }
}

// ---------------------------------------------------------------------------
// QKV projection: grid (32, 8, 3), block 256
// z=0: Q = (query@Wq+bq)*0.125 -> g_Q ; z=1: K -> g_K ; z=2: V -> g_V
// output layout [B,H,T,hd]
// ---------------------------------------------------------------------------
__global__ __launch_bounds__(256, 2)
void qkv_kernel(const float* __restrict__ q, const float* __restrict__ k,
                const float* __restrict__ v,
                const float* __restrict__ Wq, const float* __restrict__ Wk,
                const float* __restrict__ Wv,
                const float* __restrict__ bq, const float* __restrict__ bk,
                const float* __restrict__ bv)
{
    extern __shared__ float sm[];
    float* Asm = sm;
    float* Wsm = sm + 2 * ASZ;

    const int z = blockIdx.z;
    const float* X    = (z == 0) ? q  : (z == 1) ? k  : v;
    const float* W    = (z == 0) ? Wq : (z == 1) ? Wk : Wv;
    const float* bias = (z == 0) ? bq : (z == 1) ? bk : bv;
    float* Out        = (z == 0) ? g_Q : (z == 1) ? g_K : g_V;
    const float scale = (z == 0) ? 0.125f : 1.0f;   // hd^-0.5 folded into Q

    const int m0 = blockIdx.x * 128;
    const int n0 = blockIdx.y * 128;

    float acc[2][8][4];
    gemm128x128(X, W, m0, n0, Asm, Wsm, acc);

    const int lane = threadIdx.x & 31;
    const int w    = threadIdx.x >> 5;
    const int wm   = w >> 1, wn = w & 1;
    const int gr   = lane >> 2, gq = lane & 3;

#pragma unroll
    for (int nt = 0; nt < 8; nt++) {
        int col = n0 + wn * 64 + nt * 8 + gq * 2;
        float b0 = __ldg(bias + col);
        float b1 = __ldg(bias + col + 1);
        int h = col >> 6, d = col & 63;
#pragma unroll
        for (int mt = 0; mt < 2; mt++) {
#pragma unroll
            for (int half = 0; half < 2; half++) {
                int row = m0 + wm * 32 + mt * 16 + gr + half * 8;
                int bi = row >> 11, t = row & (TT - 1);
                float2 val;
                val.x = (acc[mt][nt][half * 2 + 0] + b0) * scale;
                val.y = (acc[mt][nt][half * 2 + 1] + b1) * scale;
                *(float2*)(Out + ((((size_t)(bi * HH + h)) * TT + t) << 6) + d) = val;
            }
        }
    }
}

// ---------------------------------------------------------------------------
// Output projection: out = g_O @ Wo + bo, grid (32,8), block 256
// ---------------------------------------------------------------------------
__global__ __launch_bounds__(256, 2)
void out_kernel(const float* __restrict__ Wo, const float* __restrict__ bo,
                float* __restrict__ out)
{
    extern __shared__ float sm[];
    float* Asm = sm;
    float* Wsm = sm + 2 * ASZ;

    const int m0 = blockIdx.x * 128;
    const int n0 = blockIdx.y * 128;

    float acc[2][8][4];
    gemm128x128(g_O, Wo, m0, n0, Asm, Wsm, acc);

    const int lane = threadIdx.x & 31;
    const int w    = threadIdx.x >> 5;
    const int wm   = w >> 1, wn = w & 1;
    const int gr   = lane >> 2, gq = lane & 3;

#pragma unroll
    for (int nt = 0; nt < 8; nt++) {
        int col = n0 + wn * 64 + nt * 8 + gq * 2;
        float b0 = __ldg(bo + col);
        float b1 = __ldg(bo + col + 1);
#pragma unroll
        for (int mt = 0; mt < 2; mt++) {
#pragma unroll
            for (int half = 0; half < 2; half++) {
                int row = m0 + wm * 32 + mt * 16 + gr + half * 8;
                float2 val;
                val.x = acc[mt][nt][half * 2 + 0] + b0;
                val.y = acc[mt][nt][half * 2 + 1] + b1;
                *(float2*)(out + (size_t)row * DD + col) = val;
            }
        }
    }
}

// ---------------------------------------------------------------------------
// Flash attention with ALiBi. grid (T/128=16, H=16, B=2), block 256 (8 warps).
// Each warp owns 16 q-rows; O/m/l entirely register-resident.
// K tile (64x64, stride 68), V tile (64x64, stride 72), warp-private P patch.
// ---------------------------------------------------------------------------
#define LDK 68
#define LDV 72
#define LDP 68
#define ATTN_SMEM_BYTES ((64*LDK + 64*LDV + 8*16*LDP)*4)   // 70656

__global__ __launch_bounds__(256, 2)
void attn_kernel()
{
    extern __shared__ float sm[];
    float* Ksm = sm;                        // 64*68
    float* Vsm = sm + 64 * LDK;             // 64*72
    float* Psm = sm + 64 * LDK + 64 * LDV;  // 8*16*68

    const int qt = blockIdx.x;   // 16 tiles of 128 q-rows
    const int h  = blockIdx.y;
    const int b  = blockIdx.z;

    const int tid  = threadIdx.x;
    const int lane = tid & 31;
    const int w    = tid >> 5;
    const int gr   = lane >> 2;   // 0..7
    const int gq   = lane & 3;    // 0..3

    const float slope = exp2f(-0.5f * (float)(h + 1));
    const int q0 = qt * 128;

    const float* Qb = g_Q + (((size_t)(b * HH + h)) * TT + q0 + w * 16) * HD;
    const float* Kb = g_K + (((size_t)(b * HH + h)) * TT) * HD;
    const float* Vb = g_V + (((size_t)(b * HH + h)) * TT) * HD;

    // Q fragments (already scaled by 1/8), converted to tf32 once
    uint32_t qf[8][4];
#pragma unroll
    for (int kk = 0; kk < 8; kk++) {
        qf[kk][0] = f2tf(Qb[(gr)     * HD + kk * 8 + gq]);
        qf[kk][1] = f2tf(Qb[(gr + 8) * HD + kk * 8 + gq]);
        qf[kk][2] = f2tf(Qb[(gr)     * HD + kk * 8 + gq + 4]);
        qf[kk][3] = f2tf(Qb[(gr + 8) * HD + kk * 8 + gq + 4]);
    }

    float oacc[8][4];
#pragma unroll
    for (int nt = 0; nt < 8; nt++)
#pragma unroll
        for (int i = 0; i < 4; i++) oacc[nt][i] = 0.0f;

    float m_lo = -INFINITY, m_hi = -INFINITY;
    float l_lo = 0.0f, l_hi = 0.0f;

    const int qrow_lo = q0 + w * 16 + gr;
    const int qrow_hi = qrow_lo + 8;
    float* Pw = Psm + w * 16 * LDP;

#pragma unroll 1
    for (int kt = 0; kt < TT / 64; kt++) {
        __syncthreads();   // everyone done with previous K/V/P
        const float4* Kg = (const float4*)(Kb + (size_t)kt * 64 * HD);
        const float4* Vg = (const float4*)(Vb + (size_t)kt * 64 * HD);
#pragma unroll
        for (int i = tid; i < 1024; i += 256) {
            int r = i >> 4, c = (i & 15) << 2;
            float4 kx = Kg[i];
            float4 kc = make_float4(tff(kx.x), tff(kx.y), tff(kx.z), tff(kx.w));
            *(float4*)(Ksm + r * LDK + c) = kc;
            float4 vx = Vg[i];
            float4 vc = make_float4(tff(vx.x), tff(vx.y), tff(vx.z), tff(vx.w));
            *(float4*)(Vsm + r * LDV + c) = vc;
        }
        __syncthreads();

        // ---- S = Q @ K^T : per warp 16x64 in registers ----
        float sacc[8][4];
#pragma unroll
        for (int nt = 0; nt < 8; nt++) {
            sacc[nt][0] = sacc[nt][1] = sacc[nt][2] = sacc[nt][3] = 0.0f;
#pragma unroll
            for (int kk = 0; kk < 8; kk++) {
                uint32_t b0 = fbits(Ksm[(nt * 8 + gr) * LDK + kk * 8 + gq]);
                uint32_t b1 = fbits(Ksm[(nt * 8 + gr) * LDK + kk * 8 + gq + 4]);
                mma_tf32(sacc[nt], qf[kk], b0, b1);
            }
        }

        // ---- ALiBi bias + row max (register softmax) ----
        float mx_lo = -INFINITY, mx_hi = -INFINITY;
        const int jb = kt * 64 + gq * 2;
#pragma unroll
        for (int nt = 0; nt < 8; nt++) {
            float j0 = (float)(jb + nt * 8);
            float j1 = j0 + 1.0f;
            sacc[nt][0] -= slope * fabsf((float)qrow_lo - j0);
            sacc[nt][1] -= slope * fabsf((float)qrow_lo - j1);
            sacc[nt][2] -= slope * fabsf((float)qrow_hi - j0);
            sacc[nt][3] -= slope * fabsf((float)qrow_hi - j1);
            mx_lo = fmaxf(mx_lo, fmaxf(sacc[nt][0], sacc[nt][1]));
            mx_hi = fmaxf(mx_hi, fmaxf(sacc[nt][2], sacc[nt][3]));
        }
        mx_lo = fmaxf(mx_lo, __shfl_xor_sync(0xffffffffu, mx_lo, 1));
        mx_lo = fmaxf(mx_lo, __shfl_xor_sync(0xffffffffu, mx_lo, 2));
        mx_hi = fmaxf(mx_hi, __shfl_xor_sync(0xffffffffu, mx_hi, 1));
        mx_hi = fmaxf(mx_hi, __shfl_xor_sync(0xffffffffu, mx_hi, 2));

        float mn_lo = fmaxf(m_lo, mx_lo);
        float mn_hi = fmaxf(m_hi, mx_hi);
        float corr_lo = __expf(m_lo - mn_lo);
        float corr_hi = __expf(m_hi - mn_hi);
        m_lo = mn_lo; m_hi = mn_hi;

        float s_lo = 0.0f, s_hi = 0.0f;
#pragma unroll
        for (int nt = 0; nt < 8; nt++) {
            float p0 = __expf(sacc[nt][0] - mn_lo);
            float p1 = __expf(sacc[nt][1] - mn_lo);
            float p2 = __expf(sacc[nt][2] - mn_hi);
            float p3 = __expf(sacc[nt][3] - mn_hi);
            s_lo += p0 + p1;
            s_hi += p2 + p3;
            *(float2*)(Pw + (gr)     * LDP + nt * 8 + gq * 2) = make_float2(tff(p0), tff(p1));
            *(float2*)(Pw + (gr + 8) * LDP + nt * 8 + gq * 2) = make_float2(tff(p2), tff(p3));
        }
        s_lo += __shfl_xor_sync(0xffffffffu, s_lo, 1);
        s_lo += __shfl_xor_sync(0xffffffffu, s_lo, 2);
        s_hi += __shfl_xor_sync(0xffffffffu, s_hi, 1);
        s_hi += __shfl_xor_sync(0xffffffffu, s_hi, 2);
        l_lo = l_lo * corr_lo + s_lo;
        l_hi = l_hi * corr_hi + s_hi;

        // rescale O in registers
#pragma unroll
        for (int nt = 0; nt < 8; nt++) {
            oacc[nt][0] *= corr_lo;
            oacc[nt][1] *= corr_lo;
            oacc[nt][2] *= corr_hi;
            oacc[nt][3] *= corr_hi;
        }
        __syncwarp();

        // ---- O += P @ V ----
#pragma unroll
        for (int kk = 0; kk < 8; kk++) {
            uint32_t a[4];
            a[0] = fbits(Pw[(gr)     * LDP + kk * 8 + gq]);
            a[1] = fbits(Pw[(gr + 8) * LDP + kk * 8 + gq]);
            a[2] = fbits(Pw[(gr)     * LDP + kk * 8 + gq + 4]);
            a[3] = fbits(Pw[(gr + 8) * LDP + kk * 8 + gq + 4]);
#pragma unroll
            for (int nt = 0; nt < 8; nt++) {
                uint32_t b0 = fbits(Vsm[(kk * 8 + gq)     * LDV + nt * 8 + gr]);
                uint32_t b1 = fbits(Vsm[(kk * 8 + gq + 4) * LDV + nt * 8 + gr]);
                mma_tf32(oacc[nt], a, b0, b1);
            }
        }
    }

    // epilogue: O /= l, write to g_O [B*T, D] at head column h*64
    float inv_lo = 1.0f / l_lo;
    float inv_hi = 1.0f / l_hi;
    float* Ob = g_O + ((size_t)(b * TT + q0 + w * 16)) * DD + h * HD;
#pragma unroll
    for (int nt = 0; nt < 8; nt++) {
        float2 vlo, vhi;
        vlo.x = oacc[nt][0] * inv_lo;
        vlo.y = oacc[nt][1] * inv_lo;
        vhi.x = oacc[nt][2] * inv_hi;
        vhi.y = oacc[nt][3] * inv_hi;
        *(float2*)(Ob + (size_t)(gr)     * DD + nt * 8 + gq * 2) = vlo;
        *(float2*)(Ob + (size_t)(gr + 8) * DD + nt * 8 + gq * 2) = vhi;
    }
}

// ---------------------------------------------------------------------------
extern "C" void kernel_launch(void* const* d_in, const int* in_sizes, int n_in,
                              void* d_out, int out_size)
{
    const float* query = (const float*)d_in[0];
    const float* key_  = (const float*)d_in[1];
    const float* value = (const float*)d_in[2];
    const float* Wq    = (const float*)d_in[3];
    const float* bq    = (const float*)d_in[4];
    const float* Wk    = (const float*)d_in[5];
    const float* bk    = (const float*)d_in[6];
    const float* Wv    = (const float*)d_in[7];
    const float* bv    = (const float*)d_in[8];
    const float* Wo    = (const float*)d_in[9];
    const float* bo    = (const float*)d_in[10];
    float* out = (float*)d_out;

    static int attr_done = 0;
    if (!attr_done) {
        cudaFuncSetAttribute(qkv_kernel, cudaFuncAttributeMaxDynamicSharedMemorySize,
                             GEMM_SMEM_BYTES);
        cudaFuncSetAttribute(out_kernel, cudaFuncAttributeMaxDynamicSharedMemorySize,
                             GEMM_SMEM_BYTES);
        cudaFuncSetAttribute(attn_kernel, cudaFuncAttributeMaxDynamicSharedMemorySize,
                             ATTN_SMEM_BYTES);
        attr_done = 1;
    }

    dim3 gqkv(MROWS / 128, DD / 128, 3);
    qkv_kernel<<<gqkv, 256, GEMM_SMEM_BYTES>>>(query, key_, value, Wq, Wk, Wv, bq, bk, bv);

    dim3 gattn(TT / 128, HH, BB);
    attn_kernel<<<gattn, 256, ATTN_SMEM_BYTES>>>();

    dim3 gout(MROWS / 128, DD / 128);
    out_kernel<<<gout, 256, GEMM_SMEM_BYTES>>>(Wo, bo, out);
}

// round 4
// speedup vs baseline: 4.6884x; 1.1433x over previous
#include <cuda_runtime.h>
#include <cuda_bf16.h>
#include <math.h>
#include <stdint.h>

// Problem constants
#define BB 2
#define TT 2048
#define DD 1024
#define HH 16
#define HD 64
#define MROWS (BB*TT)        // 4096

// Scratch (device globals; allocation is forbidden)
__device__ float g_Q[BB*HH*TT*HD];   // [B,H,T,hd], pre-scaled by 1/8
__device__ float g_K[BB*HH*TT*HD];
__device__ float g_V[BB*HH*TT*HD];
__device__ float g_O[MROWS*DD];      // [B*T, D]

// ---------------------------------------------------------------------------
// tf32 helpers + raw mma
// ---------------------------------------------------------------------------
__device__ __forceinline__ uint32_t f2tf(float x) {
    uint32_t r;
    asm("cvt.rna.tf32.f32 %0, %1;" : "=r"(r) : "f"(x));
    return r;
}
__device__ __forceinline__ float tff(float x) { return __uint_as_float(f2tf(x)); }
__device__ __forceinline__ uint32_t fbits(float x) { return __float_as_uint(x); }

// D = A(16x8,row) * B(8x8,col) + D, tf32 in, f32 out
__device__ __forceinline__ void mma_tf32(float c[4], const uint32_t a[4],
                                         uint32_t b0, uint32_t b1) {
    asm volatile(
        "mma.sync.aligned.m16n8k8.row.col.f32.tf32.tf32.f32 "
        "{%0,%1,%2,%3},{%4,%5,%6,%7},{%8,%9},{%0,%1,%2,%3};\n"
        : "+f"(c[0]), "+f"(c[1]), "+f"(c[2]), "+f"(c[3])
        : "r"(a[0]), "r"(a[1]), "r"(a[2]), "r"(a[3]), "r"(b0), "r"(b1));
}

// ---------------------------------------------------------------------------
// GEMM core: 128x128 block tile, BK=32, double-buffered.
// 256 threads = 8 warps arranged 4(m) x 2(n); warp tile 32x64.
// Asm: [2][128][36] (36 = 4 mod 32 -> conflict-free A-frag loads)
// Wsm: [2][32][136] (136 = 8 mod 32 -> conflict-free B-frag loads)
// ---------------------------------------------------------------------------
#define LDA 36
#define LDW 136
#define ASZ (128*LDA)
#define WSZ (32*LDW)
#define GEMM_SMEM_BYTES ((2*(ASZ+WSZ))*4)   // 71680

__device__ __forceinline__ void gemm128x128(
    const float* __restrict__ X, const float* __restrict__ W,
    int m0, int n0, float* Asm, float* Wsm, float acc[2][8][4])
{
    const int tid  = threadIdx.x;
    const int lane = tid & 31;
    const int w    = tid >> 5;
    const int wm   = w >> 1;      // 0..3
    const int wn   = w & 1;       // 0..1
    const int gr   = lane >> 2;   // 0..7
    const int gq   = lane & 3;    // 0..3

#pragma unroll
    for (int mt = 0; mt < 2; mt++)
#pragma unroll
        for (int nt = 0; nt < 8; nt++)
#pragma unroll
            for (int i = 0; i < 4; i++) acc[mt][nt][i] = 0.0f;

    float4 ar[4], wr[4];

    // loaders: A tile 128x32 (1024 float4), W tile 32x128 (1024 float4)
    auto LDGA = [&](int k0) {
#pragma unroll
        for (int j = 0; j < 4; j++) {
            int f  = tid + j * 256;
            int r  = f >> 3, c  = (f & 7) << 2;
            ar[j] = *(const float4*)(X + (size_t)(m0 + r) * DD + k0 + c);
            int rw = f >> 5, cw = (f & 31) << 2;
            wr[j] = *(const float4*)(W + (size_t)(k0 + rw) * DD + n0 + cw);
        }
    };
    auto STS = [&](int buf) {
        float* Ab = Asm + buf * ASZ;
        float* Wb = Wsm + buf * WSZ;
#pragma unroll
        for (int j = 0; j < 4; j++) {
            int f = tid + j * 256;
            int r = f >> 3, c = (f & 7) << 2;
            float4 v = ar[j];
            float4 vt = make_float4(tff(v.x), tff(v.y), tff(v.z), tff(v.w));
            *(float4*)(Ab + r * LDA + c) = vt;
            int rw = f >> 5, cw = (f & 31) << 2;
            float4 u = wr[j];
            float4 ut = make_float4(tff(u.x), tff(u.y), tff(u.z), tff(u.w));
            *(float4*)(Wb + rw * LDW + cw) = ut;
        }
    };

    LDGA(0);
    STS(0);
    __syncthreads();

#pragma unroll 1
    for (int s = 0; s < 32; s++) {
        if (s < 31) LDGA((s + 1) * 32);

        const float* Ab = Asm + (s & 1) * ASZ;
        const float* Wb = Wsm + (s & 1) * WSZ;

#pragma unroll
        for (int ks = 0; ks < 4; ks++) {
            uint32_t a[2][4];
#pragma unroll
            for (int mt = 0; mt < 2; mt++) {
                int r = wm * 32 + mt * 16;
                a[mt][0] = fbits(Ab[(r + gr)     * LDA + ks * 8 + gq]);
                a[mt][1] = fbits(Ab[(r + 8 + gr) * LDA + ks * 8 + gq]);
                a[mt][2] = fbits(Ab[(r + gr)     * LDA + ks * 8 + gq + 4]);
                a[mt][3] = fbits(Ab[(r + 8 + gr) * LDA + ks * 8 + gq + 4]);
            }
#pragma unroll
            for (int nt = 0; nt < 8; nt++) {
                int col = wn * 64 + nt * 8;
                uint32_t b0 = fbits(Wb[(ks * 8 + gq)     * LDW + col + gr]);
                uint32_t b1 = fbits(Wb[(ks * 8 + gq + 4) * LDW + col + gr]);
                mma_tf32(acc[0][nt], a[0], b0, b1);
                mma_tf32(acc[1][nt], a[1], b0, b1);
            }
        }
        if (s < 31) STS((s + 1) & 1);
        __syncthreads();
    }
}

// ---------------------------------------------------------------------------
// QKV projection: grid (32, 8, 3), block 256
// z=0: Q = (query@Wq+bq)*0.125 -> g_Q ; z=1: K -> g_K ; z=2: V -> g_V
// output layout [B,H,T,hd]
// ---------------------------------------------------------------------------
__global__ __launch_bounds__(256, 2)
void qkv_kernel(const float* __restrict__ q, const float* __restrict__ k,
                const float* __restrict__ v,
                const float* __restrict__ Wq, const float* __restrict__ Wk,
                const float* __restrict__ Wv,
                const float* __restrict__ bq, const float* __restrict__ bk,
                const float* __restrict__ bv)
{
    extern __shared__ float sm[];
    float* Asm = sm;
    float* Wsm = sm + 2 * ASZ;

    const int z = blockIdx.z;
    const float* X    = (z == 0) ? q  : (z == 1) ? k  : v;
    const float* W    = (z == 0) ? Wq : (z == 1) ? Wk : Wv;
    const float* bias = (z == 0) ? bq : (z == 1) ? bk : bv;
    float* Out        = (z == 0) ? g_Q : (z == 1) ? g_K : g_V;
    const float scale = (z == 0) ? 0.125f : 1.0f;   // hd^-0.5 folded into Q

    const int m0 = blockIdx.x * 128;
    const int n0 = blockIdx.y * 128;

    float acc[2][8][4];
    gemm128x128(X, W, m0, n0, Asm, Wsm, acc);

    const int lane = threadIdx.x & 31;
    const int w    = threadIdx.x >> 5;
    const int wm   = w >> 1, wn = w & 1;
    const int gr   = lane >> 2, gq = lane & 3;

#pragma unroll
    for (int nt = 0; nt < 8; nt++) {
        int col = n0 + wn * 64 + nt * 8 + gq * 2;
        float b0 = __ldg(bias + col);
        float b1 = __ldg(bias + col + 1);
        int h = col >> 6, d = col & 63;
#pragma unroll
        for (int mt = 0; mt < 2; mt++) {
#pragma unroll
            for (int half = 0; half < 2; half++) {
                int row = m0 + wm * 32 + mt * 16 + gr + half * 8;
                int bi = row >> 11, t = row & (TT - 1);
                float2 val;
                val.x = (acc[mt][nt][half * 2 + 0] + b0) * scale;
                val.y = (acc[mt][nt][half * 2 + 1] + b1) * scale;
                *(float2*)(Out + ((((size_t)(bi * HH + h)) * TT + t) << 6) + d) = val;
            }
        }
    }
}

// ---------------------------------------------------------------------------
// Output projection: out = g_O @ Wo + bo, grid (32,8), block 256
// ---------------------------------------------------------------------------
__global__ __launch_bounds__(256, 2)
void out_kernel(const float* __restrict__ Wo, const float* __restrict__ bo,
                float* __restrict__ out)
{
    extern __shared__ float sm[];
    float* Asm = sm;
    float* Wsm = sm + 2 * ASZ;

    const int m0 = blockIdx.x * 128;
    const int n0 = blockIdx.y * 128;

    float acc[2][8][4];
    gemm128x128(g_O, Wo, m0, n0, Asm, Wsm, acc);

    const int lane = threadIdx.x & 31;
    const int w    = threadIdx.x >> 5;
    const int wm   = w >> 1, wn = w & 1;
    const int gr   = lane >> 2, gq = lane & 3;

#pragma unroll
    for (int nt = 0; nt < 8; nt++) {
        int col = n0 + wn * 64 + nt * 8 + gq * 2;
        float b0 = __ldg(bo + col);
        float b1 = __ldg(bo + col + 1);
#pragma unroll
        for (int mt = 0; mt < 2; mt++) {
#pragma unroll
            for (int half = 0; half < 2; half++) {
                int row = m0 + wm * 32 + mt * 16 + gr + half * 8;
                float2 val;
                val.x = acc[mt][nt][half * 2 + 0] + b0;
                val.y = acc[mt][nt][half * 2 + 1] + b1;
                *(float2*)(out + (size_t)row * DD + col) = val;
            }
        }
    }
}

// ---------------------------------------------------------------------------
// Flash attention with ALiBi + band skipping.
// grid (T/128=16, H=16, B=2), block 256 (8 warps).
// Tiles with slope*dist_min > ALIBI_MARGIN contribute < ~3e-8 relative mass
// (row max >= diagonal score, score spread <= ~10) and are skipped entirely.
// ---------------------------------------------------------------------------
#define LDK 68
#define LDV 72
#define LDP 68
#define ALIBI_MARGIN 35.0f
#define ATTN_SMEM_BYTES ((64*LDK + 64*LDV + 8*16*LDP)*4)   // 70656

__global__ __launch_bounds__(256, 2)
void attn_kernel()
{
    extern __shared__ float sm[];
    float* Ksm = sm;                        // 64*68
    float* Vsm = sm + 64 * LDK;             // 64*72
    float* Psm = sm + 64 * LDK + 64 * LDV;  // 8*16*68

    const int qt = blockIdx.x;
    const int h  = blockIdx.y;
    const int b  = blockIdx.z;

    const int tid  = threadIdx.x;
    const int lane = tid & 31;
    const int w    = tid >> 5;
    const int gr   = lane >> 2;
    const int gq   = lane & 3;

    const float slope = exp2f(-0.5f * (float)(h + 1));
    const int q0 = qt * 128;

    // band limits: only k-tiles within distance band of [q0, q0+127] matter
    const int band  = (int)(ALIBI_MARGIN / slope);
    const int kt_lo = max(0, (q0 - band) >> 6);
    const int kt_hi = min(TT / 64 - 1, (q0 + 127 + band) >> 6);

    const float* Qb = g_Q + (((size_t)(b * HH + h)) * TT + q0 + w * 16) * HD;
    const float* Kb = g_K + (((size_t)(b * HH + h)) * TT) * HD;
    const float* Vb = g_V + (((size_t)(b * HH + h)) * TT) * HD;

    uint32_t qf[8][4];
#pragma unroll
    for (int kk = 0; kk < 8; kk++) {
        qf[kk][0] = f2tf(Qb[(gr)     * HD + kk * 8 + gq]);
        qf[kk][1] = f2tf(Qb[(gr + 8) * HD + kk * 8 + gq]);
        qf[kk][2] = f2tf(Qb[(gr)     * HD + kk * 8 + gq + 4]);
        qf[kk][3] = f2tf(Qb[(gr + 8) * HD + kk * 8 + gq + 4]);
    }

    float oacc[8][4];
#pragma unroll
    for (int nt = 0; nt < 8; nt++)
#pragma unroll
        for (int i = 0; i < 4; i++) oacc[nt][i] = 0.0f;

    float m_lo = -INFINITY, m_hi = -INFINITY;
    float l_lo = 0.0f, l_hi = 0.0f;

    const int qrow_lo = q0 + w * 16 + gr;
    const int qrow_hi = qrow_lo + 8;
    float* Pw = Psm + w * 16 * LDP;

#pragma unroll 1
    for (int kt = kt_lo; kt <= kt_hi; kt++) {
        __syncthreads();
        const float4* Kg = (const float4*)(Kb + (size_t)kt * 64 * HD);
        const float4* Vg = (const float4*)(Vb + (size_t)kt * 64 * HD);
#pragma unroll
        for (int i = tid; i < 1024; i += 256) {
            int r = i >> 4, c = (i & 15) << 2;
            float4 kx = Kg[i];
            float4 kc = make_float4(tff(kx.x), tff(kx.y), tff(kx.z), tff(kx.w));
            *(float4*)(Ksm + r * LDK + c) = kc;
            float4 vx = Vg[i];
            float4 vc = make_float4(tff(vx.x), tff(vx.y), tff(vx.z), tff(vx.w));
            *(float4*)(Vsm + r * LDV + c) = vc;
        }
        __syncthreads();

        float sacc[8][4];
#pragma unroll
        for (int nt = 0; nt < 8; nt++) {
            sacc[nt][0] = sacc[nt][1] = sacc[nt][2] = sacc[nt][3] = 0.0f;
#pragma unroll
            for (int kk = 0; kk < 8; kk++) {
                uint32_t b0 = fbits(Ksm[(nt * 8 + gr) * LDK + kk * 8 + gq]);
                uint32_t b1 = fbits(Ksm[(nt * 8 + gr) * LDK + kk * 8 + gq + 4]);
                mma_tf32(sacc[nt], qf[kk], b0, b1);
            }
        }

        float mx_lo = -INFINITY, mx_hi = -INFINITY;
        const int jb = kt * 64 + gq * 2;
#pragma unroll
        for (int nt = 0; nt < 8; nt++) {
            float j0 = (float)(jb + nt * 8);
            float j1 = j0 + 1.0f;
            sacc[nt][0] -= slope * fabsf((float)qrow_lo - j0);
            sacc[nt][1] -= slope * fabsf((float)qrow_lo - j1);
            sacc[nt][2] -= slope * fabsf((float)qrow_hi - j0);
            sacc[nt][3] -= slope * fabsf((float)qrow_hi - j1);
            mx_lo = fmaxf(mx_lo, fmaxf(sacc[nt][0], sacc[nt][1]));
            mx_hi = fmaxf(mx_hi, fmaxf(sacc[nt][2], sacc[nt][3]));
        }
        mx_lo = fmaxf(mx_lo, __shfl_xor_sync(0xffffffffu, mx_lo, 1));
        mx_lo = fmaxf(mx_lo, __shfl_xor_sync(0xffffffffu, mx_lo, 2));
        mx_hi = fmaxf(mx_hi, __shfl_xor_sync(0xffffffffu, mx_hi, 1));
        mx_hi = fmaxf(mx_hi, __shfl_xor_sync(0xffffffffu, mx_hi, 2));

        float mn_lo = fmaxf(m_lo, mx_lo);
        float mn_hi = fmaxf(m_hi, mx_hi);
        float corr_lo = __expf(m_lo - mn_lo);
        float corr_hi = __expf(m_hi - mn_hi);
        m_lo = mn_lo; m_hi = mn_hi;

        float s_lo = 0.0f, s_hi = 0.0f;
#pragma unroll
        for (int nt = 0; nt < 8; nt++) {
            float p0 = __expf(sacc[nt][0] - mn_lo);
            float p1 = __expf(sacc[nt][1] - mn_lo);
            float p2 = __expf(sacc[nt][2] - mn_hi);
            float p3 = __expf(sacc[nt][3] - mn_hi);
            s_lo += p0 + p1;
            s_hi += p2 + p3;
            *(float2*)(Pw + (gr)     * LDP + nt * 8 + gq * 2) = make_float2(tff(p0), tff(p1));
            *(float2*)(Pw + (gr + 8) * LDP + nt * 8 + gq * 2) = make_float2(tff(p2), tff(p3));
        }
        s_lo += __shfl_xor_sync(0xffffffffu, s_lo, 1);
        s_lo += __shfl_xor_sync(0xffffffffu, s_lo, 2);
        s_hi += __shfl_xor_sync(0xffffffffu, s_hi, 1);
        s_hi += __shfl_xor_sync(0xffffffffu, s_hi, 2);
        l_lo = l_lo * corr_lo + s_lo;
        l_hi = l_hi * corr_hi + s_hi;

#pragma unroll
        for (int nt = 0; nt < 8; nt++) {
            oacc[nt][0] *= corr_lo;
            oacc[nt][1] *= corr_lo;
            oacc[nt][2] *= corr_hi;
            oacc[nt][3] *= corr_hi;
        }
        __syncwarp();

#pragma unroll
        for (int kk = 0; kk < 8; kk++) {
            uint32_t a[4];
            a[0] = fbits(Pw[(gr)     * LDP + kk * 8 + gq]);
            a[1] = fbits(Pw[(gr + 8) * LDP + kk * 8 + gq]);
            a[2] = fbits(Pw[(gr)     * LDP + kk * 8 + gq + 4]);
            a[3] = fbits(Pw[(gr + 8) * LDP + kk * 8 + gq + 4]);
#pragma unroll
            for (int nt = 0; nt < 8; nt++) {
                uint32_t b0 = fbits(Vsm[(kk * 8 + gq)     * LDV + nt * 8 + gr]);
                uint32_t b1 = fbits(Vsm[(kk * 8 + gq + 4) * LDV + nt * 8 + gr]);
                mma_tf32(oacc[nt], a, b0, b1);
            }
        }
    }

    float inv_lo = 1.0f / l_lo;
    float inv_hi = 1.0f / l_hi;
    float* Ob = g_O + ((size_t)(b * TT + q0 + w * 16)) * DD + h * HD;
#pragma unroll
    for (int nt = 0; nt < 8; nt++) {
        float2 vlo, vhi;
        vlo.x = oacc[nt][0] * inv_lo;
        vlo.y = oacc[nt][1] * inv_lo;
        vhi.x = oacc[nt][2] * inv_hi;
        vhi.y = oacc[nt][3] * inv_hi;
        *(float2*)(Ob + (size_t)(gr)     * DD + nt * 8 + gq * 2) = vlo;
        *(float2*)(Ob + (size_t)(gr + 8) * DD + nt * 8 + gq * 2) = vhi;
    }
}

// ---------------------------------------------------------------------------
extern "C" void kernel_launch(void* const* d_in, const int* in_sizes, int n_in,
                              void* d_out, int out_size)
{
    const float* query = (const float*)d_in[0];
    const float* key_  = (const float*)d_in[1];
    const float* value = (const float*)d_in[2];
    const float* Wq    = (const float*)d_in[3];
    const float* bq    = (const float*)d_in[4];
    const float* Wk    = (const float*)d_in[5];
    const float* bk    = (const float*)d_in[6];
    const float* Wv    = (const float*)d_in[7];
    const float* bv    = (const float*)d_in[8];
    const float* Wo    = (const float*)d_in[9];
    const float* bo    = (const float*)d_in[10];
    float* out = (float*)d_out;

    static int attr_done = 0;
    if (!attr_done) {
        cudaFuncSetAttribute(qkv_kernel, cudaFuncAttributeMaxDynamicSharedMemorySize,
                             GEMM_SMEM_BYTES);
        cudaFuncSetAttribute(out_kernel, cudaFuncAttributeMaxDynamicSharedMemorySize,
                             GEMM_SMEM_BYTES);
        cudaFuncSetAttribute(attn_kernel, cudaFuncAttributeMaxDynamicSharedMemorySize,
                             ATTN_SMEM_BYTES);
        attr_done = 1;
    }

    dim3 gqkv(MROWS / 128, DD / 128, 3);
    qkv_kernel<<<gqkv, 256, GEMM_SMEM_BYTES>>>(query, key_, value, Wq, Wk, Wv, bq, bk, bv);

    dim3 gattn(TT / 128, HH, BB);
    attn_kernel<<<gattn, 256, ATTN_SMEM_BYTES>>>();

    dim3 gout(MROWS / 128, DD / 128);
    out_kernel<<<gout, 256, GEMM_SMEM_BYTES>>>(Wo, bo, out);
}

// round 5
// speedup vs baseline: 5.4344x; 1.1591x over previous
#include <cuda_runtime.h>
#include <cuda_bf16.h>
#include <math.h>
#include <stdint.h>

// Problem constants
#define BB 2
#define TT 2048
#define DD 1024
#define HH 16
#define HD 64
#define MROWS (BB*TT)        // 4096
#define LOG2E 1.44269504088896340736f

// Scratch (device globals; allocation is forbidden)
__device__ float g_Q[BB*HH*TT*HD];   // [B,H,T,hd], scaled by 0.125*log2e, tf32-rounded
__device__ float g_K[BB*HH*TT*HD];   // tf32-rounded
__device__ float g_V[BB*HH*TT*HD];   // tf32-rounded
__device__ float g_O[MROWS*DD];      // [B*T, D], tf32-rounded
__device__ float g_Xr[3*MROWS*DD];   // tf32-rounded query/key/value
__device__ float g_Wr[4*DD*DD];      // tf32-rounded Wq/Wk/Wv/Wo

// ---------------------------------------------------------------------------
// helpers
// ---------------------------------------------------------------------------
__device__ __forceinline__ uint32_t smem_u32(const void* p) {
    uint32_t a;
    asm("{ .reg .u64 t; cvta.to.shared.u64 t, %1; cvt.u32.u64 %0, t; }"
        : "=r"(a) : "l"(p));
    return a;
}
__device__ __forceinline__ uint32_t f2tf(float x) {
    uint32_t r;
    asm("cvt.rna.tf32.f32 %0, %1;" : "=r"(r) : "f"(x));
    return r;
}
__device__ __forceinline__ float tff(float x) { return __uint_as_float(f2tf(x)); }
__device__ __forceinline__ uint32_t fbits(float x) { return __float_as_uint(x); }
__device__ __forceinline__ float ex2(float x) {
    float y;
    asm("ex2.approx.f32 %0, %1;" : "=f"(y) : "f"(x));
    return y;
}

__device__ __forceinline__ void cp16(uint32_t dst, const float* src) {
    asm volatile("cp.async.cg.shared.global [%0], [%1], 16;"
                 :: "r"(dst), "l"(src));
}
#define CP_COMMIT() asm volatile("cp.async.commit_group;" ::: "memory")
#define CP_WAIT(N)  asm volatile("cp.async.wait_group %0;" :: "n"(N) : "memory")

// D = A(16x8,row) * B(8x8,col) + D, tf32 in, f32 out
__device__ __forceinline__ void mma_tf32(float c[4], const uint32_t a[4],
                                         uint32_t b0, uint32_t b1) {
    asm volatile(
        "mma.sync.aligned.m16n8k8.row.col.f32.tf32.tf32.f32 "
        "{%0,%1,%2,%3},{%4,%5,%6,%7},{%8,%9},{%0,%1,%2,%3};\n"
        : "+f"(c[0]), "+f"(c[1]), "+f"(c[2]), "+f"(c[3])
        : "r"(a[0]), "r"(a[1]), "r"(a[2]), "r"(a[3]), "r"(b0), "r"(b1));
}

// ---------------------------------------------------------------------------
// Pre-round pass: tf32-round inputs (X) and weights (W) once.
// ---------------------------------------------------------------------------
__global__ __launch_bounds__(256)
void round_x(const float4* __restrict__ q, const float4* __restrict__ k,
             const float4* __restrict__ v)
{
    const int z = blockIdx.z;
    const float4* src = (z == 0) ? q : (z == 1) ? k : v;
    float4* dst = (float4*)(g_Xr + (size_t)z * MROWS * DD);
    int i = blockIdx.x * 256 + threadIdx.x;
    float4 a = src[i];
    dst[i] = make_float4(tff(a.x), tff(a.y), tff(a.z), tff(a.w));
}

__global__ __launch_bounds__(256)
void round_w(const float4* __restrict__ w0, const float4* __restrict__ w1,
             const float4* __restrict__ w2, const float4* __restrict__ w3)
{
    const int z = blockIdx.z;
    const float4* src = (z == 0) ? w0 : (z == 1) ? w1 : (z == 2) ? w2 : w3;
    float4* dst = (float4*)(g_Wr + (size_t)z * DD * DD);
    int i = blockIdx.x * 256 + threadIdx.x;
    float4 a = src[i];
    dst[i] = make_float4(tff(a.x), tff(a.y), tff(a.z), tff(a.w));
}

// ---------------------------------------------------------------------------
// GEMM core: 128x128 tile, BK=32, 3-stage cp.async pipeline.
// Inputs must be pre-rounded to tf32. 256 threads = 8 warps (4m x 2n).
// A stage: [128][36] floats (144B row stride, 16B aligned, %32=4 pad)
// B stage: [32][136] floats (544B row stride, %32=8 pad)
// ---------------------------------------------------------------------------
#define LDA 36
#define LDW 136
#define ASTG (128*LDA)            // 4608 floats
#define BSTG (32*LDW)             // 4352 floats
#define STG  (ASTG+BSTG)          // 8960 floats
#define GEMM_SMEM_BYTES (3*STG*4) // 107520

__device__ __forceinline__ void gemm128x128(
    const float* __restrict__ X, const float* __restrict__ W,
    int m0, int n0, float* sm, float acc[2][8][4])
{
    const int tid  = threadIdx.x;
    const int lane = tid & 31;
    const int w    = tid >> 5;
    const int wm   = w >> 1;
    const int wn   = w & 1;
    const int gr   = lane >> 2;
    const int gq   = lane & 3;

    const uint32_t sbase = smem_u32(sm);

#pragma unroll
    for (int mt = 0; mt < 2; mt++)
#pragma unroll
        for (int nt = 0; nt < 8; nt++)
#pragma unroll
            for (int i = 0; i < 4; i++) acc[mt][nt][i] = 0.0f;

    auto ISSUE = [&](int s) {
        const int k0 = s * 32;
        const uint32_t Ab = sbase + (uint32_t)((s % 3) * STG) * 4;
        const uint32_t Bb = Ab + ASTG * 4;
#pragma unroll
        for (int j = 0; j < 4; j++) {
            const int f = tid + j * 256;
            // A: 128 rows x 8 chunks of 16B
            const int ra = f >> 3, ca = f & 7;
            cp16(Ab + (uint32_t)(ra * LDA + ca * 4) * 4,
                 X + (size_t)(m0 + ra) * DD + k0 + ca * 4);
            // B: 32 rows x 32 chunks of 16B
            const int rb = f >> 5, cb = f & 31;
            cp16(Bb + (uint32_t)(rb * LDW + cb * 4) * 4,
                 W + (size_t)(k0 + rb) * DD + n0 + cb * 4);
        }
    };

    ISSUE(0); CP_COMMIT();
    ISSUE(1); CP_COMMIT();

#pragma unroll 1
    for (int s = 0; s < 32; s++) {
        CP_WAIT(1);          // stage s resident (s+1 may be in flight)
        __syncthreads();     // visibility + all warps done with stage s-1
        if (s + 2 < 32) ISSUE(s + 2);
        CP_COMMIT();

        const float* Ab = sm + (s % 3) * STG;
        const float* Wb = Ab + ASTG;

#pragma unroll
        for (int ks = 0; ks < 4; ks++) {
            uint32_t a[2][4];
#pragma unroll
            for (int mt = 0; mt < 2; mt++) {
                int r = wm * 32 + mt * 16;
                a[mt][0] = fbits(Ab[(r + gr)     * LDA + ks * 8 + gq]);
                a[mt][1] = fbits(Ab[(r + 8 + gr) * LDA + ks * 8 + gq]);
                a[mt][2] = fbits(Ab[(r + gr)     * LDA + ks * 8 + gq + 4]);
                a[mt][3] = fbits(Ab[(r + 8 + gr) * LDA + ks * 8 + gq + 4]);
            }
#pragma unroll
            for (int nt = 0; nt < 8; nt++) {
                int col = wn * 64 + nt * 8;
                uint32_t b0 = fbits(Wb[(ks * 8 + gq)     * LDW + col + gr]);
                uint32_t b1 = fbits(Wb[(ks * 8 + gq + 4) * LDW + col + gr]);
                mma_tf32(acc[0][nt], a[0], b0, b1);
                mma_tf32(acc[1][nt], a[1], b0, b1);
            }
        }
    }
}

// ---------------------------------------------------------------------------
// QKV projection: grid (32, 8, 3), block 256.
// Outputs tf32-rounded; Q additionally scaled by 0.125*log2e (log2-domain).
// ---------------------------------------------------------------------------
__global__ __launch_bounds__(256, 2)
void qkv_kernel(const float* __restrict__ bq, const float* __restrict__ bk,
                const float* __restrict__ bv)
{
    extern __shared__ float sm[];
    const int z = blockIdx.z;
    const float* X    = g_Xr + (size_t)z * MROWS * DD;
    const float* W    = g_Wr + (size_t)z * DD * DD;
    const float* bias = (z == 0) ? bq : (z == 1) ? bk : bv;
    float* Out        = (z == 0) ? g_Q : (z == 1) ? g_K : g_V;
    const float scale = (z == 0) ? 0.125f * LOG2E : 1.0f;

    const int m0 = blockIdx.x * 128;
    const int n0 = blockIdx.y * 128;

    float acc[2][8][4];
    gemm128x128(X, W, m0, n0, sm, acc);

    const int lane = threadIdx.x & 31;
    const int w    = threadIdx.x >> 5;
    const int wm   = w >> 1, wn = w & 1;
    const int gr   = lane >> 2, gq = lane & 3;

#pragma unroll
    for (int nt = 0; nt < 8; nt++) {
        int col = n0 + wn * 64 + nt * 8 + gq * 2;
        float b0 = __ldg(bias + col);
        float b1 = __ldg(bias + col + 1);
        int h = col >> 6, d = col & 63;
#pragma unroll
        for (int mt = 0; mt < 2; mt++) {
#pragma unroll
            for (int half = 0; half < 2; half++) {
                int row = m0 + wm * 32 + mt * 16 + gr + half * 8;
                int bi = row >> 11, t = row & (TT - 1);
                float2 val;
                val.x = tff((acc[mt][nt][half * 2 + 0] + b0) * scale);
                val.y = tff((acc[mt][nt][half * 2 + 1] + b1) * scale);
                *(float2*)(Out + ((((size_t)(bi * HH + h)) * TT + t) << 6) + d) = val;
            }
        }
    }
}

// ---------------------------------------------------------------------------
// Output projection: out = g_O @ Wo + bo (final, fp32 out)
// ---------------------------------------------------------------------------
__global__ __launch_bounds__(256, 2)
void out_kernel(const float* __restrict__ bo, float* __restrict__ out)
{
    extern __shared__ float sm[];
    const int m0 = blockIdx.x * 128;
    const int n0 = blockIdx.y * 128;

    float acc[2][8][4];
    gemm128x128(g_O, g_Wr + (size_t)3 * DD * DD, m0, n0, sm, acc);

    const int lane = threadIdx.x & 31;
    const int w    = threadIdx.x >> 5;
    const int wm   = w >> 1, wn = w & 1;
    const int gr   = lane >> 2, gq = lane & 3;

#pragma unroll
    for (int nt = 0; nt < 8; nt++) {
        int col = n0 + wn * 64 + nt * 8 + gq * 2;
        float b0 = __ldg(bo + col);
        float b1 = __ldg(bo + col + 1);
#pragma unroll
        for (int mt = 0; mt < 2; mt++) {
#pragma unroll
            for (int half = 0; half < 2; half++) {
                int row = m0 + wm * 32 + mt * 16 + gr + half * 8;
                float2 val;
                val.x = acc[mt][nt][half * 2 + 0] + b0;
                val.y = acc[mt][nt][half * 2 + 1] + b1;
                *(float2*)(out + (size_t)row * DD + col) = val;
            }
        }
    }
}

// ---------------------------------------------------------------------------
// Flash attention, log2-domain softmax, ALiBi band skipping, cp.async
// double-buffered K/V. grid (16, 16, 2), block 256 (8 warps).
// ---------------------------------------------------------------------------
#define LDK 68
#define LDV 72
#define LDP 68
#define KVSTG (64*LDK + 64*LDV)   // 8960 floats per buffer
#define ALIBI_MARGIN 35.0f
#define ATTN_SMEM_BYTES ((2*KVSTG + 8*16*LDP)*4)   // 106496

__global__ __launch_bounds__(256, 2)
void attn_kernel()
{
    extern __shared__ float sm[];
    float* Psm = sm + 2 * KVSTG;

    const int qt = blockIdx.x;
    const int h  = HH - 1 - blockIdx.y;   // heavy heads first
    const int b  = blockIdx.z;

    const int tid  = threadIdx.x;
    const int lane = tid & 31;
    const int w    = tid >> 5;
    const int gr   = lane >> 2;
    const int gq   = lane & 3;

    const float slope    = exp2f(-0.5f * (float)(h + 1));
    const float slope_l2 = slope * LOG2E;
    const int q0 = qt * 128;

    const int band  = (int)(ALIBI_MARGIN / slope);
    const int kt_lo = max(0, (q0 - band) >> 6);
    const int kt_hi = min(TT / 64 - 1, (q0 + 127 + band) >> 6);

    const float* Qb = g_Q + (((size_t)(b * HH + h)) * TT + q0 + w * 16) * HD;
    const float* Kb = g_K + (((size_t)(b * HH + h)) * TT) * HD;
    const float* Vb = g_V + (((size_t)(b * HH + h)) * TT) * HD;

    const uint32_t sbase = smem_u32(sm);

    auto ISSUE = [&](int kt, int buf) {
        const uint32_t Kd = sbase + (uint32_t)(buf * KVSTG) * 4;
        const uint32_t Vd = Kd + (uint32_t)(64 * LDK) * 4;
        const float* Kg = Kb + (size_t)kt * 64 * HD;
        const float* Vg = Vb + (size_t)kt * 64 * HD;
#pragma unroll
        for (int j = 0; j < 4; j++) {
            const int f = tid + j * 256;
            const int r = f >> 4, c = f & 15;   // 64 rows x 16 chunks of 16B
            cp16(Kd + (uint32_t)(r * LDK + c * 4) * 4, Kg + r * HD + c * 4);
            cp16(Vd + (uint32_t)(r * LDV + c * 4) * 4, Vg + r * HD + c * 4);
        }
    };

    // Q fragments: pre-rounded & pre-scaled (0.125*log2e)
    uint32_t qf[8][4];
#pragma unroll
    for (int kk = 0; kk < 8; kk++) {
        qf[kk][0] = fbits(Qb[(gr)     * HD + kk * 8 + gq]);
        qf[kk][1] = fbits(Qb[(gr + 8) * HD + kk * 8 + gq]);
        qf[kk][2] = fbits(Qb[(gr)     * HD + kk * 8 + gq + 4]);
        qf[kk][3] = fbits(Qb[(gr + 8) * HD + kk * 8 + gq + 4]);
    }

    float oacc[8][4];
#pragma unroll
    for (int nt = 0; nt < 8; nt++)
#pragma unroll
        for (int i = 0; i < 4; i++) oacc[nt][i] = 0.0f;

    float m_lo = -INFINITY, m_hi = -INFINITY;
    float l_lo = 0.0f, l_hi = 0.0f;

    const int qrow_lo = q0 + w * 16 + gr;
    const int qrow_hi = qrow_lo + 8;
    float* Pw = Psm + w * 16 * LDP;

    ISSUE(kt_lo, 0); CP_COMMIT();

#pragma unroll 1
    for (int kt = kt_lo; kt <= kt_hi; kt++) {
        const int buf = (kt - kt_lo) & 1;
        if (kt < kt_hi) ISSUE(kt + 1, buf ^ 1);
        CP_COMMIT();
        CP_WAIT(1);
        __syncthreads();

        const float* Ksm = sm + buf * KVSTG;
        const float* Vsm = Ksm + 64 * LDK;

        // ---- S = Q @ K^T (log2 domain) ----
        float sacc[8][4];
#pragma unroll
        for (int nt = 0; nt < 8; nt++) {
            sacc[nt][0] = sacc[nt][1] = sacc[nt][2] = sacc[nt][3] = 0.0f;
#pragma unroll
            for (int kk = 0; kk < 8; kk++) {
                uint32_t b0 = fbits(Ksm[(nt * 8 + gr) * LDK + kk * 8 + gq]);
                uint32_t b1 = fbits(Ksm[(nt * 8 + gr) * LDK + kk * 8 + gq + 4]);
                mma_tf32(sacc[nt], qf[kk], b0, b1);
            }
        }

        // ---- ALiBi bias + row max ----
        float mx_lo = -INFINITY, mx_hi = -INFINITY;
        const int jb = kt * 64 + gq * 2;
#pragma unroll
        for (int nt = 0; nt < 8; nt++) {
            float j0 = (float)(jb + nt * 8);
            float j1 = j0 + 1.0f;
            sacc[nt][0] -= slope_l2 * fabsf((float)qrow_lo - j0);
            sacc[nt][1] -= slope_l2 * fabsf((float)qrow_lo - j1);
            sacc[nt][2] -= slope_l2 * fabsf((float)qrow_hi - j0);
            sacc[nt][3] -= slope_l2 * fabsf((float)qrow_hi - j1);
            mx_lo = fmaxf(mx_lo, fmaxf(sacc[nt][0], sacc[nt][1]));
            mx_hi = fmaxf(mx_hi, fmaxf(sacc[nt][2], sacc[nt][3]));
        }
        mx_lo = fmaxf(mx_lo, __shfl_xor_sync(0xffffffffu, mx_lo, 1));
        mx_lo = fmaxf(mx_lo, __shfl_xor_sync(0xffffffffu, mx_lo, 2));
        mx_hi = fmaxf(mx_hi, __shfl_xor_sync(0xffffffffu, mx_hi, 1));
        mx_hi = fmaxf(mx_hi, __shfl_xor_sync(0xffffffffu, mx_hi, 2));

        float mn_lo = fmaxf(m_lo, mx_lo);
        float mn_hi = fmaxf(m_hi, mx_hi);
        float corr_lo = ex2(m_lo - mn_lo);
        float corr_hi = ex2(m_hi - mn_hi);
        m_lo = mn_lo; m_hi = mn_hi;

        float s_lo = 0.0f, s_hi = 0.0f;
#pragma unroll
        for (int nt = 0; nt < 8; nt++) {
            float p0 = ex2(sacc[nt][0] - mn_lo);
            float p1 = ex2(sacc[nt][1] - mn_lo);
            float p2 = ex2(sacc[nt][2] - mn_hi);
            float p3 = ex2(sacc[nt][3] - mn_hi);
            s_lo += p0 + p1;
            s_hi += p2 + p3;
            *(float2*)(Pw + (gr)     * LDP + nt * 8 + gq * 2) = make_float2(tff(p0), tff(p1));
            *(float2*)(Pw + (gr + 8) * LDP + nt * 8 + gq * 2) = make_float2(tff(p2), tff(p3));
        }
        s_lo += __shfl_xor_sync(0xffffffffu, s_lo, 1);
        s_lo += __shfl_xor_sync(0xffffffffu, s_lo, 2);
        s_hi += __shfl_xor_sync(0xffffffffu, s_hi, 1);
        s_hi += __shfl_xor_sync(0xffffffffu, s_hi, 2);
        l_lo = l_lo * corr_lo + s_lo;
        l_hi = l_hi * corr_hi + s_hi;

#pragma unroll
        for (int nt = 0; nt < 8; nt++) {
            oacc[nt][0] *= corr_lo;
            oacc[nt][1] *= corr_lo;
            oacc[nt][2] *= corr_hi;
            oacc[nt][3] *= corr_hi;
        }
        __syncwarp();

        // ---- O += P @ V ----
#pragma unroll
        for (int kk = 0; kk < 8; kk++) {
            uint32_t a[4];
            a[0] = fbits(Pw[(gr)     * LDP + kk * 8 + gq]);
            a[1] = fbits(Pw[(gr + 8) * LDP + kk * 8 + gq]);
            a[2] = fbits(Pw[(gr)     * LDP + kk * 8 + gq + 4]);
            a[3] = fbits(Pw[(gr + 8) * LDP + kk * 8 + gq + 4]);
#pragma unroll
            for (int nt = 0; nt < 8; nt++) {
                uint32_t b0 = fbits(Vsm[(kk * 8 + gq)     * LDV + nt * 8 + gr]);
                uint32_t b1 = fbits(Vsm[(kk * 8 + gq + 4) * LDV + nt * 8 + gr]);
                mma_tf32(oacc[nt], a, b0, b1);
            }
        }
        __syncthreads();   // all warps done with buf before it is refilled
    }

    // epilogue: O /= l, tf32-rounded for the downstream cp.async GEMM
    float inv_lo = 1.0f / l_lo;
    float inv_hi = 1.0f / l_hi;
    float* Ob = g_O + ((size_t)(b * TT + q0 + w * 16)) * DD + h * HD;
#pragma unroll
    for (int nt = 0; nt < 8; nt++) {
        float2 vlo, vhi;
        vlo.x = tff(oacc[nt][0] * inv_lo);
        vlo.y = tff(oacc[nt][1] * inv_lo);
        vhi.x = tff(oacc[nt][2] * inv_hi);
        vhi.y = tff(oacc[nt][3] * inv_hi);
        *(float2*)(Ob + (size_t)(gr)     * DD + nt * 8 + gq * 2) = vlo;
        *(float2*)(Ob + (size_t)(gr + 8) * DD + nt * 8 + gq * 2) = vhi;
    }
}

// ---------------------------------------------------------------------------
extern "C" void kernel_launch(void* const* d_in, const int* in_sizes, int n_in,
                              void* d_out, int out_size)
{
    const float* query = (const float*)d_in[0];
    const float* key_  = (const float*)d_in[1];
    const float* value = (const float*)d_in[2];
    const float* Wq    = (const float*)d_in[3];
    const float* bq    = (const float*)d_in[4];
    const float* Wk    = (const float*)d_in[5];
    const float* bk    = (const float*)d_in[6];
    const float* Wv    = (const float*)d_in[7];
    const float* bv    = (const float*)d_in[8];
    const float* Wo    = (const float*)d_in[9];
    const float* bo    = (const float*)d_in[10];
    float* out = (float*)d_out;

    static int attr_done = 0;
    if (!attr_done) {
        cudaFuncSetAttribute(qkv_kernel, cudaFuncAttributeMaxDynamicSharedMemorySize,
                             GEMM_SMEM_BYTES);
        cudaFuncSetAttribute(out_kernel, cudaFuncAttributeMaxDynamicSharedMemorySize,
                             GEMM_SMEM_BYTES);
        cudaFuncSetAttribute(attn_kernel, cudaFuncAttributeMaxDynamicSharedMemorySize,
                             ATTN_SMEM_BYTES);
        attr_done = 1;
    }

    round_x<<<dim3(MROWS * DD / 1024, 1, 3), 256>>>(
        (const float4*)query, (const float4*)key_, (const float4*)value);
    round_w<<<dim3(DD * DD / 1024, 1, 4), 256>>>(
        (const float4*)Wq, (const float4*)Wk, (const float4*)Wv, (const float4*)Wo);

    dim3 gqkv(MROWS / 128, DD / 128, 3);
    qkv_kernel<<<gqkv, 256, GEMM_SMEM_BYTES>>>(bq, bk, bv);

    dim3 gattn(TT / 128, HH, BB);
    attn_kernel<<<gattn, 256, ATTN_SMEM_BYTES>>>();

    dim3 gout(MROWS / 128, DD / 128);
    out_kernel<<<gout, 256, GEMM_SMEM_BYTES>>>(bo, out);
}

// round 6
// speedup vs baseline: 10.2931x; 1.8941x over previous
#include <cuda_runtime.h>
#include <cuda_fp16.h>
#include <math.h>
#include <stdint.h>

// Problem constants
#define BB 2
#define TT 2048
#define DD 1024
#define HH 16
#define HD 64
#define MROWS (BB*TT)        // 4096
#define LOG2E 1.44269504088896340736f

// Scratch (device globals; allocation is forbidden). All fp16.
__device__ __half g_Q[BB*HH*TT*HD];   // [B,H,T,hd], scaled by 0.125*log2e
__device__ __half g_K[BB*HH*TT*HD];
__device__ __half g_V[BB*HH*TT*HD];
__device__ __half g_O[MROWS*DD];      // [B*T, D]
__device__ __half g_Xh[3*MROWS*DD];   // fp16 query/key/value
__device__ __half g_Wh[4*DD*DD];      // fp16 Wq/Wk/Wv/Wo

// ---------------------------------------------------------------------------
// helpers
// ---------------------------------------------------------------------------
__device__ __forceinline__ uint32_t smem_u32(const void* p) {
    uint32_t a;
    asm("{ .reg .u64 t; cvta.to.shared.u64 t, %1; cvt.u32.u64 %0, t; }"
        : "=r"(a) : "l"(p));
    return a;
}
// pack two floats into half2 (lo = first arg)
__device__ __forceinline__ uint32_t h2pack(float lo, float hi) {
    uint32_t r;
    asm("cvt.rn.f16x2.f32 %0, %1, %2;" : "=r"(r) : "f"(hi), "f"(lo));
    return r;
}
__device__ __forceinline__ float ex2(float x) {
    float y;
    asm("ex2.approx.f32 %0, %1;" : "=f"(y) : "f"(x));
    return y;
}
__device__ __forceinline__ void cp16(uint32_t dst, const void* src) {
    asm volatile("cp.async.cg.shared.global [%0], [%1], 16;"
                 :: "r"(dst), "l"(src));
}
#define CP_COMMIT() asm volatile("cp.async.commit_group;" ::: "memory")
#define CP_WAIT(N)  asm volatile("cp.async.wait_group %0;" :: "n"(N) : "memory")

__device__ __forceinline__ void ldm_x4(uint32_t r[4], uint32_t addr) {
    asm volatile("ldmatrix.sync.aligned.m8n8.x4.shared.b16 {%0,%1,%2,%3}, [%4];"
                 : "=r"(r[0]), "=r"(r[1]), "=r"(r[2]), "=r"(r[3]) : "r"(addr));
}
__device__ __forceinline__ void ldm_x4t(uint32_t r[4], uint32_t addr) {
    asm volatile("ldmatrix.sync.aligned.m8n8.x4.trans.shared.b16 {%0,%1,%2,%3}, [%4];"
                 : "=r"(r[0]), "=r"(r[1]), "=r"(r[2]), "=r"(r[3]) : "r"(addr));
}
// D += A(16x16) * B(16x8), fp16 in, f32 accum
__device__ __forceinline__ void mma_f16(float c[4], const uint32_t a[4],
                                        uint32_t b0, uint32_t b1) {
    asm volatile(
        "mma.sync.aligned.m16n8k16.row.col.f32.f16.f16.f32 "
        "{%0,%1,%2,%3},{%4,%5,%6,%7},{%8,%9},{%0,%1,%2,%3};\n"
        : "+f"(c[0]), "+f"(c[1]), "+f"(c[2]), "+f"(c[3])
        : "r"(a[0]), "r"(a[1]), "r"(a[2]), "r"(a[3]), "r"(b0), "r"(b1));
}

// ---------------------------------------------------------------------------
// Pre-pass: convert inputs and weights to fp16 once.
// ---------------------------------------------------------------------------
__global__ __launch_bounds__(256)
void round_x(const float4* __restrict__ q, const float4* __restrict__ k,
             const float4* __restrict__ v)
{
    const int z = blockIdx.z;
    const float4* src = (z == 0) ? q : (z == 1) ? k : v;
    uint4* dst = (uint4*)(g_Xh + (size_t)z * MROWS * DD);
    int i = blockIdx.x * 256 + threadIdx.x;
    float4 a = src[2 * i], b = src[2 * i + 1];
    uint4 o;
    o.x = h2pack(a.x, a.y); o.y = h2pack(a.z, a.w);
    o.z = h2pack(b.x, b.y); o.w = h2pack(b.z, b.w);
    dst[i] = o;
}

__global__ __launch_bounds__(256)
void round_w(const float4* __restrict__ w0, const float4* __restrict__ w1,
             const float4* __restrict__ w2, const float4* __restrict__ w3)
{
    const int z = blockIdx.z;
    const float4* src = (z == 0) ? w0 : (z == 1) ? w1 : (z == 2) ? w2 : w3;
    uint4* dst = (uint4*)(g_Wh + (size_t)z * DD * DD);
    int i = blockIdx.x * 256 + threadIdx.x;
    float4 a = src[2 * i], b = src[2 * i + 1];
    uint4 o;
    o.x = h2pack(a.x, a.y); o.y = h2pack(a.z, a.w);
    o.z = h2pack(b.x, b.y); o.w = h2pack(b.z, b.w);
    dst[i] = o;
}

// ---------------------------------------------------------------------------
// fp16 GEMM core: 128x128 tile, BK=32, 3-stage cp.async, ldmatrix frags.
// 256 threads = 8 warps (4m x 2n), warp tile 32x64.
// A stage: [128][40] halves (80B rows); B stage: [32][136] halves (272B rows)
// ---------------------------------------------------------------------------
#define LDA 40
#define LDW 136
#define ASTG (128*LDA)             // 5120 halves
#define BSTG (32*LDW)              // 4352 halves
#define STG  (ASTG+BSTG)           // 9472 halves
#define GEMM_SMEM_BYTES (3*STG*2)  // 56832

__device__ __forceinline__ void gemm128x128(
    const __half* __restrict__ X, const __half* __restrict__ W,
    int m0, int n0, __half* sm, float acc[2][8][4])
{
    const int tid  = threadIdx.x;
    const int lane = tid & 31;
    const int w    = tid >> 5;
    const int wm   = w >> 1;
    const int wn   = w & 1;

    const uint32_t sbase = smem_u32(sm);

#pragma unroll
    for (int mt = 0; mt < 2; mt++)
#pragma unroll
        for (int nt = 0; nt < 8; nt++)
#pragma unroll
            for (int i = 0; i < 4; i++) acc[mt][nt][i] = 0.0f;

    auto ISSUE = [&](int s) {
        const int k0 = s * 32;
        const uint32_t Ab = sbase + (uint32_t)((s % 3) * STG) * 2;
        const uint32_t Bb = Ab + ASTG * 2;
#pragma unroll
        for (int j = 0; j < 2; j++) {
            const int f = tid + j * 256;
            // A: 128 rows x 4 chunks of 16B (8 halves)
            const int ra = f >> 2, ca = f & 3;
            cp16(Ab + (uint32_t)(ra * LDA + ca * 8) * 2,
                 X + (size_t)(m0 + ra) * DD + k0 + ca * 8);
            // B: 32 rows x 16 chunks of 16B
            const int rb = f >> 4, cb = f & 15;
            cp16(Bb + (uint32_t)(rb * LDW + cb * 8) * 2,
                 W + (size_t)(k0 + rb) * DD + n0 + cb * 8);
        }
    };

    ISSUE(0); CP_COMMIT();
    ISSUE(1); CP_COMMIT();

    const int lrow = lane & 15;
    const int lcol = (lane >> 4) << 3;

#pragma unroll 1
    for (int s = 0; s < 32; s++) {
        CP_WAIT(1);
        __syncthreads();
        if (s + 2 < 32) ISSUE(s + 2);
        CP_COMMIT();

        const uint32_t Ab = sbase + (uint32_t)((s % 3) * STG) * 2;
        const uint32_t Bb = Ab + ASTG * 2;

#pragma unroll
        for (int kk = 0; kk < 2; kk++) {
            uint32_t a[2][4];
#pragma unroll
            for (int mt = 0; mt < 2; mt++) {
                const int r = wm * 32 + mt * 16;
                ldm_x4(a[mt], Ab + (uint32_t)((r + lrow) * LDA + kk * 16 + lcol) * 2);
            }
            uint32_t bb[4][4];
#pragma unroll
            for (int np = 0; np < 4; np++) {
                const int col = wn * 64 + np * 16 + lcol;
                ldm_x4t(bb[np], Bb + (uint32_t)((kk * 16 + lrow) * LDW + col) * 2);
            }
#pragma unroll
            for (int nt = 0; nt < 8; nt++) {
                const int np = nt >> 1, o = (nt & 1) * 2;
                mma_f16(acc[0][nt], a[0], bb[np][o], bb[np][o + 1]);
                mma_f16(acc[1][nt], a[1], bb[np][o], bb[np][o + 1]);
            }
        }
    }
}

// ---------------------------------------------------------------------------
// QKV projection: grid (32, 8, 3), block 256. Outputs fp16 (Q pre-scaled).
// ---------------------------------------------------------------------------
__global__ __launch_bounds__(256, 2)
void qkv_kernel(const float* __restrict__ bq, const float* __restrict__ bk,
                const float* __restrict__ bv)
{
    extern __shared__ __half smh[];
    const int z = blockIdx.z;
    const __half* X   = g_Xh + (size_t)z * MROWS * DD;
    const __half* W   = g_Wh + (size_t)z * DD * DD;
    const float* bias = (z == 0) ? bq : (z == 1) ? bk : bv;
    __half* Out       = (z == 0) ? g_Q : (z == 1) ? g_K : g_V;
    const float scale = (z == 0) ? 0.125f * LOG2E : 1.0f;

    const int m0 = blockIdx.x * 128;
    const int n0 = blockIdx.y * 128;

    float acc[2][8][4];
    gemm128x128(X, W, m0, n0, smh, acc);

    const int lane = threadIdx.x & 31;
    const int w    = threadIdx.x >> 5;
    const int wm   = w >> 1, wn = w & 1;
    const int gr   = lane >> 2, gq = lane & 3;

#pragma unroll
    for (int nt = 0; nt < 8; nt++) {
        int col = n0 + wn * 64 + nt * 8 + gq * 2;
        float b0 = __ldg(bias + col);
        float b1 = __ldg(bias + col + 1);
        int h = col >> 6, d = col & 63;
#pragma unroll
        for (int mt = 0; mt < 2; mt++) {
#pragma unroll
            for (int half = 0; half < 2; half++) {
                int row = m0 + wm * 32 + mt * 16 + gr + half * 8;
                int bi = row >> 11, t = row & (TT - 1);
                uint32_t val = h2pack((acc[mt][nt][half * 2 + 0] + b0) * scale,
                                      (acc[mt][nt][half * 2 + 1] + b1) * scale);
                *(uint32_t*)(Out + ((((size_t)(bi * HH + h)) * TT + t) << 6) + d) = val;
            }
        }
    }
}

// ---------------------------------------------------------------------------
// Output projection: out = g_O @ Wo + bo (final, fp32 out)
// ---------------------------------------------------------------------------
__global__ __launch_bounds__(256, 2)
void out_kernel(const float* __restrict__ bo, float* __restrict__ out)
{
    extern __shared__ __half smh[];
    const int m0 = blockIdx.x * 128;
    const int n0 = blockIdx.y * 128;

    float acc[2][8][4];
    gemm128x128(g_O, g_Wh + (size_t)3 * DD * DD, m0, n0, smh, acc);

    const int lane = threadIdx.x & 31;
    const int w    = threadIdx.x >> 5;
    const int wm   = w >> 1, wn = w & 1;
    const int gr   = lane >> 2, gq = lane & 3;

#pragma unroll
    for (int nt = 0; nt < 8; nt++) {
        int col = n0 + wn * 64 + nt * 8 + gq * 2;
        float b0 = __ldg(bo + col);
        float b1 = __ldg(bo + col + 1);
#pragma unroll
        for (int mt = 0; mt < 2; mt++) {
#pragma unroll
            for (int half = 0; half < 2; half++) {
                int row = m0 + wm * 32 + mt * 16 + gr + half * 8;
                float2 val;
                val.x = acc[mt][nt][half * 2 + 0] + b0;
                val.y = acc[mt][nt][half * 2 + 1] + b1;
                *(float2*)(out + (size_t)row * DD + col) = val;
            }
        }
    }
}

// ---------------------------------------------------------------------------
// fp16 flash attention, log2-domain softmax, ALiBi band skipping.
// grid (16, 16, 2), block 256 (8 warps, 16 q-rows each).
// P fragments converted in registers (no smem round trip).
// ---------------------------------------------------------------------------
#define LDK 72
#define LDV 72
#define KVH (64*LDK + 64*LDV)          // 9216 halves per buffer
#define ALIBI_MARGIN 35.0f
#define ATTN_SMEM_BYTES (2*KVH*2)      // 36864

__global__ __launch_bounds__(256, 2)
void attn_kernel()
{
    extern __shared__ __half smh[];

    const int qt = blockIdx.x;
    const int h  = HH - 1 - blockIdx.y;   // heavy heads first
    const int b  = blockIdx.z;

    const int tid  = threadIdx.x;
    const int lane = tid & 31;
    const int w    = tid >> 5;
    const int gr   = lane >> 2;
    const int gq   = lane & 3;

    const float slope    = exp2f(-0.5f * (float)(h + 1));
    const float slope_l2 = slope * LOG2E;
    const int q0 = qt * 128;

    const int band  = (int)(ALIBI_MARGIN / slope);
    const int kt_lo = max(0, (q0 - band) >> 6);
    const int kt_hi = min(TT / 64 - 1, (q0 + 127 + band) >> 6);

    const __half* Qb = g_Q + (((size_t)(b * HH + h)) * TT + q0 + w * 16) * HD;
    const __half* Kb = g_K + (((size_t)(b * HH + h)) * TT) * HD;
    const __half* Vb = g_V + (((size_t)(b * HH + h)) * TT) * HD;

    const uint32_t sbase = smem_u32(smh);

    auto ISSUE = [&](int kt, int buf) {
        const uint32_t Kd = sbase + (uint32_t)(buf * KVH) * 2;
        const uint32_t Vd = Kd + (uint32_t)(64 * LDK) * 2;
        const __half* Kg = Kb + (size_t)kt * 64 * HD;
        const __half* Vg = Vb + (size_t)kt * 64 * HD;
#pragma unroll
        for (int j = 0; j < 2; j++) {
            const int f = tid + j * 256;
            const int r = f >> 3, c = f & 7;   // 64 rows x 8 chunks of 16B
            cp16(Kd + (uint32_t)(r * LDK + c * 8) * 2, Kg + r * HD + c * 8);
            cp16(Vd + (uint32_t)(r * LDV + c * 8) * 2, Vg + r * HD + c * 8);
        }
    };

    // Q fragments (fp16, pre-scaled by 0.125*log2e), loaded once from gmem
    uint32_t qf[4][4];
#pragma unroll
    for (int kk = 0; kk < 4; kk++) {
        qf[kk][0] = *(const uint32_t*)(Qb + (gr)     * HD + kk * 16 + gq * 2);
        qf[kk][1] = *(const uint32_t*)(Qb + (gr + 8) * HD + kk * 16 + gq * 2);
        qf[kk][2] = *(const uint32_t*)(Qb + (gr)     * HD + kk * 16 + gq * 2 + 8);
        qf[kk][3] = *(const uint32_t*)(Qb + (gr + 8) * HD + kk * 16 + gq * 2 + 8);
    }

    float oacc[8][4];
#pragma unroll
    for (int nt = 0; nt < 8; nt++)
#pragma unroll
        for (int i = 0; i < 4; i++) oacc[nt][i] = 0.0f;

    float m_lo = -INFINITY, m_hi = -INFINITY;
    float l_lo = 0.0f, l_hi = 0.0f;

    const int qrow_lo = q0 + w * 16 + gr;
    const int qrow_hi = qrow_lo + 8;

    // ldmatrix lane addressing helpers
    const int l15 = lane & 15;
    const int l7  = lane & 7;
    const int hi16 = (lane >> 4) << 3;        // 0 or 8
    const int mid8 = ((lane >> 3) & 1) << 3;  // 0 or 8

    ISSUE(kt_lo, 0); CP_COMMIT();

#pragma unroll 1
    for (int kt = kt_lo; kt <= kt_hi; kt++) {
        const int buf = (kt - kt_lo) & 1;
        if (kt < kt_hi) ISSUE(kt + 1, buf ^ 1);
        CP_COMMIT();
        CP_WAIT(1);
        __syncthreads();

        const uint32_t Ksmb = sbase + (uint32_t)(buf * KVH) * 2;
        const uint32_t Vsmb = Ksmb + (uint32_t)(64 * LDK) * 2;

        // ---- S = Q @ K^T (log2 domain) ----
        float sacc[8][4];
#pragma unroll
        for (int nt = 0; nt < 8; nt++)
            sacc[nt][0] = sacc[nt][1] = sacc[nt][2] = sacc[nt][3] = 0.0f;

#pragma unroll
        for (int kk = 0; kk < 4; kk++) {
            uint32_t kb[4][4];
#pragma unroll
            for (int p = 0; p < 4; p++) {
                const int row = p * 16 + hi16 + l7;
                const int col = kk * 16 + mid8;
                ldm_x4(kb[p], Ksmb + (uint32_t)(row * LDK + col) * 2);
            }
#pragma unroll
            for (int nt = 0; nt < 8; nt++) {
                const int p = nt >> 1, o = (nt & 1) * 2;
                mma_f16(sacc[nt], qf[kk], kb[p][o], kb[p][o + 1]);
            }
        }

        // ---- ALiBi bias + row max ----
        float mx_lo = -INFINITY, mx_hi = -INFINITY;
        const int jb = kt * 64 + gq * 2;
#pragma unroll
        for (int nt = 0; nt < 8; nt++) {
            float j0 = (float)(jb + nt * 8);
            float j1 = j0 + 1.0f;
            sacc[nt][0] -= slope_l2 * fabsf((float)qrow_lo - j0);
            sacc[nt][1] -= slope_l2 * fabsf((float)qrow_lo - j1);
            sacc[nt][2] -= slope_l2 * fabsf((float)qrow_hi - j0);
            sacc[nt][3] -= slope_l2 * fabsf((float)qrow_hi - j1);
            mx_lo = fmaxf(mx_lo, fmaxf(sacc[nt][0], sacc[nt][1]));
            mx_hi = fmaxf(mx_hi, fmaxf(sacc[nt][2], sacc[nt][3]));
        }
        mx_lo = fmaxf(mx_lo, __shfl_xor_sync(0xffffffffu, mx_lo, 1));
        mx_lo = fmaxf(mx_lo, __shfl_xor_sync(0xffffffffu, mx_lo, 2));
        mx_hi = fmaxf(mx_hi, __shfl_xor_sync(0xffffffffu, mx_hi, 1));
        mx_hi = fmaxf(mx_hi, __shfl_xor_sync(0xffffffffu, mx_hi, 2));

        float mn_lo = fmaxf(m_lo, mx_lo);
        float mn_hi = fmaxf(m_hi, mx_hi);
        float corr_lo = ex2(m_lo - mn_lo);
        float corr_hi = ex2(m_hi - mn_hi);
        m_lo = mn_lo; m_hi = mn_hi;

        float s_lo = 0.0f, s_hi = 0.0f;
#pragma unroll
        for (int nt = 0; nt < 8; nt++) {
            sacc[nt][0] = ex2(sacc[nt][0] - mn_lo);
            sacc[nt][1] = ex2(sacc[nt][1] - mn_lo);
            sacc[nt][2] = ex2(sacc[nt][2] - mn_hi);
            sacc[nt][3] = ex2(sacc[nt][3] - mn_hi);
            s_lo += sacc[nt][0] + sacc[nt][1];
            s_hi += sacc[nt][2] + sacc[nt][3];
        }
        s_lo += __shfl_xor_sync(0xffffffffu, s_lo, 1);
        s_lo += __shfl_xor_sync(0xffffffffu, s_lo, 2);
        s_hi += __shfl_xor_sync(0xffffffffu, s_hi, 1);
        s_hi += __shfl_xor_sync(0xffffffffu, s_hi, 2);
        l_lo = l_lo * corr_lo + s_lo;
        l_hi = l_hi * corr_hi + s_hi;

#pragma unroll
        for (int nt = 0; nt < 8; nt++) {
            oacc[nt][0] *= corr_lo;
            oacc[nt][1] *= corr_lo;
            oacc[nt][2] *= corr_hi;
            oacc[nt][3] *= corr_hi;
        }

        // ---- O += P @ V : P fragments built in registers ----
#pragma unroll
        for (int kk = 0; kk < 4; kk++) {
            uint32_t pa[4];
            pa[0] = h2pack(sacc[2*kk][0],   sacc[2*kk][1]);
            pa[1] = h2pack(sacc[2*kk][2],   sacc[2*kk][3]);
            pa[2] = h2pack(sacc[2*kk+1][0], sacc[2*kk+1][1]);
            pa[3] = h2pack(sacc[2*kk+1][2], sacc[2*kk+1][3]);
            uint32_t vb[4][4];
#pragma unroll
            for (int np = 0; np < 4; np++) {
                const int row = kk * 16 + l15;
                const int col = np * 16 + hi16;
                ldm_x4t(vb[np], Vsmb + (uint32_t)(row * LDV + col) * 2);
            }
#pragma unroll
            for (int nt = 0; nt < 8; nt++) {
                const int np = nt >> 1, o = (nt & 1) * 2;
                mma_f16(oacc[nt], pa, vb[np][o], vb[np][o + 1]);
            }
        }
        __syncthreads();   // all warps done with buf before it is refilled
    }

    // epilogue: O /= l, write fp16 to g_O [B*T, D] at head column h*64
    float inv_lo = 1.0f / l_lo;
    float inv_hi = 1.0f / l_hi;
    __half* Ob = g_O + ((size_t)(b * TT + q0 + w * 16)) * DD + h * HD;
#pragma unroll
    for (int nt = 0; nt < 8; nt++) {
        *(uint32_t*)(Ob + (size_t)(gr)     * DD + nt * 8 + gq * 2) =
            h2pack(oacc[nt][0] * inv_lo, oacc[nt][1] * inv_lo);
        *(uint32_t*)(Ob + (size_t)(gr + 8) * DD + nt * 8 + gq * 2) =
            h2pack(oacc[nt][2] * inv_hi, oacc[nt][3] * inv_hi);
    }
}

// ---------------------------------------------------------------------------
extern "C" void kernel_launch(void* const* d_in, const int* in_sizes, int n_in,
                              void* d_out, int out_size)
{
    const float* query = (const float*)d_in[0];
    const float* key_  = (const float*)d_in[1];
    const float* value = (const float*)d_in[2];
    const float* Wq    = (const float*)d_in[3];
    const float* bq    = (const float*)d_in[4];
    const float* Wk    = (const float*)d_in[5];
    const float* bk    = (const float*)d_in[6];
    const float* Wv    = (const float*)d_in[7];
    const float* bv    = (const float*)d_in[8];
    const float* Wo    = (const float*)d_in[9];
    const float* bo    = (const float*)d_in[10];
    float* out = (float*)d_out;

    static int attr_done = 0;
    if (!attr_done) {
        cudaFuncSetAttribute(qkv_kernel, cudaFuncAttributeMaxDynamicSharedMemorySize,
                             GEMM_SMEM_BYTES);
        cudaFuncSetAttribute(out_kernel, cudaFuncAttributeMaxDynamicSharedMemorySize,
                             GEMM_SMEM_BYTES);
        cudaFuncSetAttribute(attn_kernel, cudaFuncAttributeMaxDynamicSharedMemorySize,
                             ATTN_SMEM_BYTES);
        attr_done = 1;
    }

    round_x<<<dim3(MROWS * DD / 2048, 1, 3), 256>>>(
        (const float4*)query, (const float4*)key_, (const float4*)value);
    round_w<<<dim3(DD * DD / 2048, 1, 4), 256>>>(
        (const float4*)Wq, (const float4*)Wk, (const float4*)Wv, (const float4*)Wo);

    dim3 gqkv(MROWS / 128, DD / 128, 3);
    qkv_kernel<<<gqkv, 256, GEMM_SMEM_BYTES>>>(bq, bk, bv);

    dim3 gattn(TT / 128, HH, BB);
    attn_kernel<<<gattn, 256, ATTN_SMEM_BYTES>>>();

    dim3 gout(MROWS / 128, DD / 128);
    out_kernel<<<gout, 256, GEMM_SMEM_BYTES>>>(bo, out);
}

// round 7
// speedup vs baseline: 10.4933x; 1.0195x over previous
#include <cuda_runtime.h>
#include <cuda_fp16.h>
#include <math.h>
#include <stdint.h>

// Problem constants
#define BB 2
#define TT 2048
#define DD 1024
#define HH 16
#define HD 64
#define MROWS (BB*TT)        // 4096
#define LOG2E 1.44269504088896340736f

// Scratch (device globals; allocation is forbidden). All fp16.
__device__ __half g_Q[BB*HH*TT*HD];   // [B,H,T,hd], scaled by 0.125*log2e
__device__ __half g_K[BB*HH*TT*HD];
__device__ __half g_V[BB*HH*TT*HD];
__device__ __half g_O[MROWS*DD];      // [B*T, D]
__device__ __half g_Xh[3*MROWS*DD];   // fp16 query/key/value
__device__ __half g_Wh[4*DD*DD];      // fp16 Wq/Wk/Wv/Wo

// ---------------------------------------------------------------------------
// helpers
// ---------------------------------------------------------------------------
__device__ __forceinline__ uint32_t smem_u32(const void* p) {
    uint32_t a;
    asm("{ .reg .u64 t; cvta.to.shared.u64 t, %1; cvt.u32.u64 %0, t; }"
        : "=r"(a) : "l"(p));
    return a;
}
// pack two floats into half2 (lo = first arg)
__device__ __forceinline__ uint32_t h2pack(float lo, float hi) {
    uint32_t r;
    asm("cvt.rn.f16x2.f32 %0, %1, %2;" : "=r"(r) : "f"(hi), "f"(lo));
    return r;
}
__device__ __forceinline__ float ex2(float x) {
    float y;
    asm("ex2.approx.f32 %0, %1;" : "=f"(y) : "f"(x));
    return y;
}
__device__ __forceinline__ void cp16(uint32_t dst, const void* src) {
    asm volatile("cp.async.cg.shared.global [%0], [%1], 16;"
                 :: "r"(dst), "l"(src));
}
#define CP_COMMIT() asm volatile("cp.async.commit_group;" ::: "memory")
#define CP_WAIT(N)  asm volatile("cp.async.wait_group %0;" :: "n"(N) : "memory")

__device__ __forceinline__ void ldm_x4(uint32_t r[4], uint32_t addr) {
    asm volatile("ldmatrix.sync.aligned.m8n8.x4.shared.b16 {%0,%1,%2,%3}, [%4];"
                 : "=r"(r[0]), "=r"(r[1]), "=r"(r[2]), "=r"(r[3]) : "r"(addr));
}
__device__ __forceinline__ void ldm_x4t(uint32_t r[4], uint32_t addr) {
    asm volatile("ldmatrix.sync.aligned.m8n8.x4.trans.shared.b16 {%0,%1,%2,%3}, [%4];"
                 : "=r"(r[0]), "=r"(r[1]), "=r"(r[2]), "=r"(r[3]) : "r"(addr));
}
// D += A(16x16) * B(16x8), fp16 in, f32 accum
__device__ __forceinline__ void mma_f16(float c[4], const uint32_t a[4],
                                        uint32_t b0, uint32_t b1) {
    asm volatile(
        "mma.sync.aligned.m16n8k16.row.col.f32.f16.f16.f32 "
        "{%0,%1,%2,%3},{%4,%5,%6,%7},{%8,%9},{%0,%1,%2,%3};\n"
        : "+f"(c[0]), "+f"(c[1]), "+f"(c[2]), "+f"(c[3])
        : "r"(a[0]), "r"(a[1]), "r"(a[2]), "r"(a[3]), "r"(b0), "r"(b1));
}

// ---------------------------------------------------------------------------
// Pre-pass: convert inputs and weights to fp16 once.
// ---------------------------------------------------------------------------
__global__ __launch_bounds__(256)
void round_x(const float4* __restrict__ q, const float4* __restrict__ k,
             const float4* __restrict__ v)
{
    const int z = blockIdx.z;
    const float4* src = (z == 0) ? q : (z == 1) ? k : v;
    uint4* dst = (uint4*)(g_Xh + (size_t)z * MROWS * DD);
    int i = blockIdx.x * 256 + threadIdx.x;
    float4 a = src[2 * i], b = src[2 * i + 1];
    uint4 o;
    o.x = h2pack(a.x, a.y); o.y = h2pack(a.z, a.w);
    o.z = h2pack(b.x, b.y); o.w = h2pack(b.z, b.w);
    dst[i] = o;
}

__global__ __launch_bounds__(256)
void round_w(const float4* __restrict__ w0, const float4* __restrict__ w1,
             const float4* __restrict__ w2, const float4* __restrict__ w3)
{
    const int z = blockIdx.z;
    const float4* src = (z == 0) ? w0 : (z == 1) ? w1 : (z == 2) ? w2 : w3;
    uint4* dst = (uint4*)(g_Wh + (size_t)z * DD * DD);
    int i = blockIdx.x * 256 + threadIdx.x;
    float4 a = src[2 * i], b = src[2 * i + 1];
    uint4 o;
    o.x = h2pack(a.x, a.y); o.y = h2pack(a.z, a.w);
    o.z = h2pack(b.x, b.y); o.w = h2pack(b.z, b.w);
    dst[i] = o;
}

// ---------------------------------------------------------------------------
// fp16 GEMM core: 128x128 tile, BK=32, 3-stage cp.async, ldmatrix frags.
// 256 threads = 8 warps (4m x 2n), warp tile 32x64.
// A stage: [128][40] halves (80B rows); B stage: [32][136] halves (272B rows)
// ---------------------------------------------------------------------------
#define LDA 40
#define LDW 136
#define ASTG (128*LDA)             // 5120 halves
#define BSTG (32*LDW)              // 4352 halves
#define STG  (ASTG+BSTG)           // 9472 halves
#define GEMM_SMEM_BYTES (3*STG*2)  // 56832

__device__ __forceinline__ void gemm128x128(
    const __half* __restrict__ X, const __half* __restrict__ W,
    int m0, int n0, __half* sm, float acc[2][8][4])
{
    const int tid  = threadIdx.x;
    const int lane = tid & 31;
    const int w    = tid >> 5;
    const int wm   = w >> 1;
    const int wn   = w & 1;

    const uint32_t sbase = smem_u32(sm);

#pragma unroll
    for (int mt = 0; mt < 2; mt++)
#pragma unroll
        for (int nt = 0; nt < 8; nt++)
#pragma unroll
            for (int i = 0; i < 4; i++) acc[mt][nt][i] = 0.0f;

    auto ISSUE = [&](int s) {
        const int k0 = s * 32;
        const uint32_t Ab = sbase + (uint32_t)((s % 3) * STG) * 2;
        const uint32_t Bb = Ab + ASTG * 2;
#pragma unroll
        for (int j = 0; j < 2; j++) {
            const int f = tid + j * 256;
            // A: 128 rows x 4 chunks of 16B (8 halves)
            const int ra = f >> 2, ca = f & 3;
            cp16(Ab + (uint32_t)(ra * LDA + ca * 8) * 2,
                 X + (size_t)(m0 + ra) * DD + k0 + ca * 8);
            // B: 32 rows x 16 chunks of 16B
            const int rb = f >> 4, cb = f & 15;
            cp16(Bb + (uint32_t)(rb * LDW + cb * 8) * 2,
                 W + (size_t)(k0 + rb) * DD + n0 + cb * 8);
        }
    };

    ISSUE(0); CP_COMMIT();
    ISSUE(1); CP_COMMIT();

    const int lrow = lane & 15;
    const int lcol = (lane >> 4) << 3;

#pragma unroll 1
    for (int s = 0; s < 32; s++) {
        CP_WAIT(1);
        __syncthreads();
        if (s + 2 < 32) ISSUE(s + 2);
        CP_COMMIT();

        const uint32_t Ab = sbase + (uint32_t)((s % 3) * STG) * 2;
        const uint32_t Bb = Ab + ASTG * 2;

#pragma unroll
        for (int kk = 0; kk < 2; kk++) {
            uint32_t a[2][4];
#pragma unroll
            for (int mt = 0; mt < 2; mt++) {
                const int r = wm * 32 + mt * 16;
                ldm_x4(a[mt], Ab + (uint32_t)((r + lrow) * LDA + kk * 16 + lcol) * 2);
            }
            uint32_t bb[4][4];
#pragma unroll
            for (int np = 0; np < 4; np++) {
                const int col = wn * 64 + np * 16 + lcol;
                ldm_x4t(bb[np], Bb + (uint32_t)((kk * 16 + lrow) * LDW + col) * 2);
            }
#pragma unroll
            for (int nt = 0; nt < 8; nt++) {
                const int np = nt >> 1, o = (nt & 1) * 2;
                mma_f16(acc[0][nt], a[0], bb[np][o], bb[np][o + 1]);
                mma_f16(acc[1][nt], a[1], bb[np][o], bb[np][o + 1]);
            }
        }
    }
}

// ---------------------------------------------------------------------------
// QKV projection: grid (32, 8, 3), block 256. Outputs fp16 (Q pre-scaled).
// ---------------------------------------------------------------------------
__global__ __launch_bounds__(256, 2)
void qkv_kernel(const float* __restrict__ bq, const float* __restrict__ bk,
                const float* __restrict__ bv)
{
    extern __shared__ __half smh[];
    const int z = blockIdx.z;
    const __half* X   = g_Xh + (size_t)z * MROWS * DD;
    const __half* W   = g_Wh + (size_t)z * DD * DD;
    const float* bias = (z == 0) ? bq : (z == 1) ? bk : bv;
    __half* Out       = (z == 0) ? g_Q : (z == 1) ? g_K : g_V;
    const float scale = (z == 0) ? 0.125f * LOG2E : 1.0f;

    const int m0 = blockIdx.x * 128;
    const int n0 = blockIdx.y * 128;

    float acc[2][8][4];
    gemm128x128(X, W, m0, n0, smh, acc);

    const int lane = threadIdx.x & 31;
    const int w    = threadIdx.x >> 5;
    const int wm   = w >> 1, wn = w & 1;
    const int gr   = lane >> 2, gq = lane & 3;

#pragma unroll
    for (int nt = 0; nt < 8; nt++) {
        int col = n0 + wn * 64 + nt * 8 + gq * 2;
        float b0 = __ldg(bias + col);
        float b1 = __ldg(bias + col + 1);
        int h = col >> 6, d = col & 63;
#pragma unroll
        for (int mt = 0; mt < 2; mt++) {
#pragma unroll
            for (int half = 0; half < 2; half++) {
                int row = m0 + wm * 32 + mt * 16 + gr + half * 8;
                int bi = row >> 11, t = row & (TT - 1);
                uint32_t val = h2pack((acc[mt][nt][half * 2 + 0] + b0) * scale,
                                      (acc[mt][nt][half * 2 + 1] + b1) * scale);
                *(uint32_t*)(Out + ((((size_t)(bi * HH + h)) * TT + t) << 6) + d) = val;
            }
        }
    }
}

// ---------------------------------------------------------------------------
// Output projection: out = g_O @ Wo + bo (final, fp32 out)
// ---------------------------------------------------------------------------
__global__ __launch_bounds__(256, 2)
void out_kernel(const float* __restrict__ bo, float* __restrict__ out)
{
    extern __shared__ __half smh[];
    const int m0 = blockIdx.x * 128;
    const int n0 = blockIdx.y * 128;

    float acc[2][8][4];
    gemm128x128(g_O, g_Wh + (size_t)3 * DD * DD, m0, n0, smh, acc);

    const int lane = threadIdx.x & 31;
    const int w    = threadIdx.x >> 5;
    const int wm   = w >> 1, wn = w & 1;
    const int gr   = lane >> 2, gq = lane & 3;

#pragma unroll
    for (int nt = 0; nt < 8; nt++) {
        int col = n0 + wn * 64 + nt * 8 + gq * 2;
        float b0 = __ldg(bo + col);
        float b1 = __ldg(bo + col + 1);
#pragma unroll
        for (int mt = 0; mt < 2; mt++) {
#pragma unroll
            for (int half = 0; half < 2; half++) {
                int row = m0 + wm * 32 + mt * 16 + gr + half * 8;
                float2 val;
                val.x = acc[mt][nt][half * 2 + 0] + b0;
                val.y = acc[mt][nt][half * 2 + 1] + b1;
                *(float2*)(out + (size_t)row * DD + col) = val;
            }
        }
    }
}

// ---------------------------------------------------------------------------
// fp16 flash attention, log2-domain softmax, ALiBi band skipping.
// grid (T/64=32, 16, 2), block 128 (4 warps, 16 q-rows each) -> 4 CTAs/SM.
// ---------------------------------------------------------------------------
#define LDK 72
#define LDV 72
#define KVH (64*LDK + 64*LDV)          // 9216 halves per buffer
#define ALIBI_MARGIN 35.0f
#define ATTN_SMEM_BYTES (2*KVH*2)      // 36864

__global__ __launch_bounds__(128, 4)
void attn_kernel()
{
    extern __shared__ __half smh[];

    const int qt = blockIdx.x;
    const int h  = HH - 1 - blockIdx.y;   // heavy heads first
    const int b  = blockIdx.z;

    const int tid  = threadIdx.x;
    const int lane = tid & 31;
    const int w    = tid >> 5;            // 0..3
    const int gr   = lane >> 2;
    const int gq   = lane & 3;

    const float slope    = exp2f(-0.5f * (float)(h + 1));
    const float slope_l2 = slope * LOG2E;
    const int q0 = qt * 64;

    const int band  = (int)(ALIBI_MARGIN / slope);
    const int kt_lo = max(0, (q0 - band) >> 6);
    const int kt_hi = min(TT / 64 - 1, (q0 + 63 + band) >> 6);

    const __half* Qb = g_Q + (((size_t)(b * HH + h)) * TT + q0 + w * 16) * HD;
    const __half* Kb = g_K + (((size_t)(b * HH + h)) * TT) * HD;
    const __half* Vb = g_V + (((size_t)(b * HH + h)) * TT) * HD;

    const uint32_t sbase = smem_u32(smh);

    auto ISSUE = [&](int kt, int buf) {
        const uint32_t Kd = sbase + (uint32_t)(buf * KVH) * 2;
        const uint32_t Vd = Kd + (uint32_t)(64 * LDK) * 2;
        const __half* Kg = Kb + (size_t)kt * 64 * HD;
        const __half* Vg = Vb + (size_t)kt * 64 * HD;
#pragma unroll
        for (int j = 0; j < 4; j++) {
            const int f = tid + j * 128;
            const int r = f >> 3, c = f & 7;   // 64 rows x 8 chunks of 16B
            cp16(Kd + (uint32_t)(r * LDK + c * 8) * 2, Kg + r * HD + c * 8);
            cp16(Vd + (uint32_t)(r * LDV + c * 8) * 2, Vg + r * HD + c * 8);
        }
    };

    // Q fragments (fp16, pre-scaled by 0.125*log2e), loaded once from gmem
    uint32_t qf[4][4];
#pragma unroll
    for (int kk = 0; kk < 4; kk++) {
        qf[kk][0] = *(const uint32_t*)(Qb + (gr)     * HD + kk * 16 + gq * 2);
        qf[kk][1] = *(const uint32_t*)(Qb + (gr + 8) * HD + kk * 16 + gq * 2);
        qf[kk][2] = *(const uint32_t*)(Qb + (gr)     * HD + kk * 16 + gq * 2 + 8);
        qf[kk][3] = *(const uint32_t*)(Qb + (gr + 8) * HD + kk * 16 + gq * 2 + 8);
    }

    float oacc[8][4];
#pragma unroll
    for (int nt = 0; nt < 8; nt++)
#pragma unroll
        for (int i = 0; i < 4; i++) oacc[nt][i] = 0.0f;

    float m_lo = -INFINITY, m_hi = -INFINITY;
    float l_lo = 0.0f, l_hi = 0.0f;

    const int qrow_lo = q0 + w * 16 + gr;
    const int qrow_hi = qrow_lo + 8;

    // ldmatrix lane addressing helpers
    const int l15 = lane & 15;
    const int l7  = lane & 7;
    const int hi16 = (lane >> 4) << 3;        // 0 or 8
    const int mid8 = ((lane >> 3) & 1) << 3;  // 0 or 8

    ISSUE(kt_lo, 0); CP_COMMIT();

#pragma unroll 1
    for (int kt = kt_lo; kt <= kt_hi; kt++) {
        const int buf = (kt - kt_lo) & 1;
        if (kt < kt_hi) ISSUE(kt + 1, buf ^ 1);
        CP_COMMIT();
        CP_WAIT(1);
        __syncthreads();

        const uint32_t Ksmb = sbase + (uint32_t)(buf * KVH) * 2;
        const uint32_t Vsmb = Ksmb + (uint32_t)(64 * LDK) * 2;

        // ---- S = Q @ K^T (log2 domain) ----
        float sacc[8][4];
#pragma unroll
        for (int nt = 0; nt < 8; nt++)
            sacc[nt][0] = sacc[nt][1] = sacc[nt][2] = sacc[nt][3] = 0.0f;

#pragma unroll
        for (int kk = 0; kk < 4; kk++) {
            uint32_t kb[4][4];
#pragma unroll
            for (int p = 0; p < 4; p++) {
                const int row = p * 16 + hi16 + l7;
                const int col = kk * 16 + mid8;
                ldm_x4(kb[p], Ksmb + (uint32_t)(row * LDK + col) * 2);
            }
#pragma unroll
            for (int nt = 0; nt < 8; nt++) {
                const int p = nt >> 1, o = (nt & 1) * 2;
                mma_f16(sacc[nt], qf[kk], kb[p][o], kb[p][o + 1]);
            }
        }

        // ---- ALiBi bias + row max ----
        float mx_lo = -INFINITY, mx_hi = -INFINITY;
        const int jb = kt * 64 + gq * 2;
#pragma unroll
        for (int nt = 0; nt < 8; nt++) {
            float j0 = (float)(jb + nt * 8);
            float j1 = j0 + 1.0f;
            sacc[nt][0] -= slope_l2 * fabsf((float)qrow_lo - j0);
            sacc[nt][1] -= slope_l2 * fabsf((float)qrow_lo - j1);
            sacc[nt][2] -= slope_l2 * fabsf((float)qrow_hi - j0);
            sacc[nt][3] -= slope_l2 * fabsf((float)qrow_hi - j1);
            mx_lo = fmaxf(mx_lo, fmaxf(sacc[nt][0], sacc[nt][1]));
            mx_hi = fmaxf(mx_hi, fmaxf(sacc[nt][2], sacc[nt][3]));
        }
        mx_lo = fmaxf(mx_lo, __shfl_xor_sync(0xffffffffu, mx_lo, 1));
        mx_lo = fmaxf(mx_lo, __shfl_xor_sync(0xffffffffu, mx_lo, 2));
        mx_hi = fmaxf(mx_hi, __shfl_xor_sync(0xffffffffu, mx_hi, 1));
        mx_hi = fmaxf(mx_hi, __shfl_xor_sync(0xffffffffu, mx_hi, 2));

        float mn_lo = fmaxf(m_lo, mx_lo);
        float mn_hi = fmaxf(m_hi, mx_hi);
        float corr_lo = ex2(m_lo - mn_lo);
        float corr_hi = ex2(m_hi - mn_hi);
        m_lo = mn_lo; m_hi = mn_hi;

        float s_lo = 0.0f, s_hi = 0.0f;
#pragma unroll
        for (int nt = 0; nt < 8; nt++) {
            sacc[nt][0] = ex2(sacc[nt][0] - mn_lo);
            sacc[nt][1] = ex2(sacc[nt][1] - mn_lo);
            sacc[nt][2] = ex2(sacc[nt][2] - mn_hi);
            sacc[nt][3] = ex2(sacc[nt][3] - mn_hi);
            s_lo += sacc[nt][0] + sacc[nt][1];
            s_hi += sacc[nt][2] + sacc[nt][3];
        }
        s_lo += __shfl_xor_sync(0xffffffffu, s_lo, 1);
        s_lo += __shfl_xor_sync(0xffffffffu, s_lo, 2);
        s_hi += __shfl_xor_sync(0xffffffffu, s_hi, 1);
        s_hi += __shfl_xor_sync(0xffffffffu, s_hi, 2);
        l_lo = l_lo * corr_lo + s_lo;
        l_hi = l_hi * corr_hi + s_hi;

#pragma unroll
        for (int nt = 0; nt < 8; nt++) {
            oacc[nt][0] *= corr_lo;
            oacc[nt][1] *= corr_lo;
            oacc[nt][2] *= corr_hi;
            oacc[nt][3] *= corr_hi;
        }

        // ---- O += P @ V : P fragments built in registers ----
#pragma unroll
        for (int kk = 0; kk < 4; kk++) {
            uint32_t pa[4];
            pa[0] = h2pack(sacc[2*kk][0],   sacc[2*kk][1]);
            pa[1] = h2pack(sacc[2*kk][2],   sacc[2*kk][3]);
            pa[2] = h2pack(sacc[2*kk+1][0], sacc[2*kk+1][1]);
            pa[3] = h2pack(sacc[2*kk+1][2], sacc[2*kk+1][3]);
            uint32_t vb[4][4];
#pragma unroll
            for (int np = 0; np < 4; np++) {
                const int row = kk * 16 + l15;
                const int col = np * 16 + hi16;
                ldm_x4t(vb[np], Vsmb + (uint32_t)(row * LDV + col) * 2);
            }
#pragma unroll
            for (int nt = 0; nt < 8; nt++) {
                const int np = nt >> 1, o = (nt & 1) * 2;
                mma_f16(oacc[nt], pa, vb[np][o], vb[np][o + 1]);
            }
        }
        __syncthreads();   // all warps done with buf before it is refilled
    }

    // epilogue: O /= l, write fp16 to g_O [B*T, D] at head column h*64
    float inv_lo = 1.0f / l_lo;
    float inv_hi = 1.0f / l_hi;
    __half* Ob = g_O + ((size_t)(b * TT + q0 + w * 16)) * DD + h * HD;
#pragma unroll
    for (int nt = 0; nt < 8; nt++) {
        *(uint32_t*)(Ob + (size_t)(gr)     * DD + nt * 8 + gq * 2) =
            h2pack(oacc[nt][0] * inv_lo, oacc[nt][1] * inv_lo);
        *(uint32_t*)(Ob + (size_t)(gr + 8) * DD + nt * 8 + gq * 2) =
            h2pack(oacc[nt][2] * inv_hi, oacc[nt][3] * inv_hi);
    }
}

// ---------------------------------------------------------------------------
extern "C" void kernel_launch(void* const* d_in, const int* in_sizes, int n_in,
                              void* d_out, int out_size)
{
    const float* query = (const float*)d_in[0];
    const float* key_  = (const float*)d_in[1];
    const float* value = (const float*)d_in[2];
    const float* Wq    = (const float*)d_in[3];
    const float* bq    = (const float*)d_in[4];
    const float* Wk    = (const float*)d_in[5];
    const float* bk    = (const float*)d_in[6];
    const float* Wv    = (const float*)d_in[7];
    const float* bv    = (const float*)d_in[8];
    const float* Wo    = (const float*)d_in[9];
    const float* bo    = (const float*)d_in[10];
    float* out = (float*)d_out;

    static int attr_done = 0;
    if (!attr_done) {
        cudaFuncSetAttribute(qkv_kernel, cudaFuncAttributeMaxDynamicSharedMemorySize,
                             GEMM_SMEM_BYTES);
        cudaFuncSetAttribute(out_kernel, cudaFuncAttributeMaxDynamicSharedMemorySize,
                             GEMM_SMEM_BYTES);
        cudaFuncSetAttribute(attn_kernel, cudaFuncAttributeMaxDynamicSharedMemorySize,
                             ATTN_SMEM_BYTES);
        attr_done = 1;
    }

    round_x<<<dim3(MROWS * DD / 2048, 1, 3), 256>>>(
        (const float4*)query, (const float4*)key_, (const float4*)value);
    round_w<<<dim3(DD * DD / 2048, 1, 4), 256>>>(
        (const float4*)Wq, (const float4*)Wk, (const float4*)Wv, (const float4*)Wo);

    dim3 gqkv(MROWS / 128, DD / 128, 3);
    qkv_kernel<<<gqkv, 256, GEMM_SMEM_BYTES>>>(bq, bk, bv);

    dim3 gattn(TT / 64, HH, BB);
    attn_kernel<<<gattn, 128, ATTN_SMEM_BYTES>>>();

    dim3 gout(MROWS / 128, DD / 128);
    out_kernel<<<gout, 256, GEMM_SMEM_BYTES>>>(bo, out);
}